// round 1
// baseline (speedup 1.0000x reference)
#include <cuda_runtime.h>
#include <math.h>

// ---------------------------------------------------------------------------
// Problem constants
// ---------------------------------------------------------------------------
#define NB   64
#define TT   800
#define HH   512
#define H2   1024
#define H3   3072   // 3*H2
#define H4   2048   // 4*H
#define OO   80
#define RR   2

typedef unsigned long long ull;

// ---------------------------------------------------------------------------
// Scratch (single __device__ array; no allocations allowed)
// ---------------------------------------------------------------------------
#define GSZ       (NB * H3)            // 196608 per gate buffer
#define OFF_GI_ATT   0
#define OFF_GH_ATT   (1 * GSZ)
#define OFF_GI_D1    (2 * GSZ)
#define OFF_GH_D1    (3 * GSZ)
#define OFF_GI_D2    (4 * GSZ)
#define OFF_GH_D2    (5 * GSZ)
#define OFF_PRE_A    (6 * GSZ)                         // 64x1024
#define OFF_PRE      (OFF_PRE_A   + NB * H2)           // 64x512
#define OFF_DP       (OFF_PRE     + NB * HH)           // 64x1024
#define OFF_RESID_SC (OFF_DP      + NB * H2)           // 64x1024
#define OFF_RESID    (OFF_RESID_SC+ NB * H2)           // 64x1024
#define OFF_RESID2   (OFF_RESID   + NB * H2)           // 64x1024
#define OFF_DECIN    (OFF_RESID2  + NB * H2)           // 64x2048
#define OFF_SCORE    (OFF_DECIN   + NB * H4)           // 64x800
#define OFF_WINV     (OFF_SCORE   + NB * TT)           // 64
#define OFF_HATT     (OFF_WINV    + 64)                // fallback h outputs
#define OFF_HD1      (OFF_HATT    + NB * H2)
#define OFF_HD2      (OFF_HD1     + NB * H2)
#define SCRATCH_TOTAL (OFF_HD2    + NB * H2)

__device__ float g_scratch[SCRATCH_TOTAL];

// ---------------------------------------------------------------------------
// Math helpers
// ---------------------------------------------------------------------------
__device__ __forceinline__ float fast_tanh(float x) {
    // accurate: 1 - 2/(e^{2x}+1); inf-safe at both ends
    float e = __expf(2.0f * x);
    return 1.0f - 2.0f / (e + 1.0f);
}
__device__ __forceinline__ float fast_sigmoid(float x) {
    return 1.0f / (1.0f + __expf(-x));
}

__device__ __forceinline__ ull pk2(float x, float y) {
    ull r;
    asm("mov.b64 %0, {%1, %2};" : "=l"(r) : "f"(x), "f"(y));
    return r;
}
__device__ __forceinline__ void upk2(ull v, float& x, float& y) {
    asm("mov.b64 {%0, %1}, %2;" : "=f"(x), "=f"(y) : "l"(v));
}
__device__ __forceinline__ void ffma2(ull& d, ull a, ull b) {
    // packed fp32 pair FMA (sm_100+): d.lo += a.lo*b.lo, d.hi += a.hi*b.hi
    asm("fma.rn.f32x2 %0, %1, %2, %0;" : "+l"(d) : "l"(a), "l"(b));
}

// ---------------------------------------------------------------------------
// Init: zero gate buffers, broadcast biases into atomically-accumulated outputs
// ---------------------------------------------------------------------------
#define INIT_TOTAL (6 * GSZ + NB * H2 + NB * HH + NB * H2 + NB * H2 + NB * RR * OO)

__global__ void init_kernel(float* __restrict__ out,
                            const float* __restrict__ b_pre1,
                            const float* __restrict__ b_pre2,
                            const float* __restrict__ b_ld,
                            const float* __restrict__ b_sc,
                            const float* __restrict__ b_out) {
    int idx = blockIdx.x * 256 + threadIdx.x;
    if (idx < 6 * GSZ) { g_scratch[idx] = 0.0f; return; }
    idx -= 6 * GSZ;
    if (idx < NB * H2) { g_scratch[OFF_PRE_A + idx] = b_pre1[idx & (H2 - 1)]; return; }
    idx -= NB * H2;
    if (idx < NB * HH) { g_scratch[OFF_PRE + idx] = b_pre2[idx & (HH - 1)]; return; }
    idx -= NB * HH;
    if (idx < NB * H2) { g_scratch[OFF_DP + idx] = b_ld[idx & (H2 - 1)]; return; }
    idx -= NB * H2;
    if (idx < NB * H2) { g_scratch[OFF_RESID_SC + idx] = b_sc[idx & (H2 - 1)]; return; }
    idx -= NB * H2;
    if (idx < NB * RR * OO) { out[idx] = b_out[idx % (RR * OO)]; return; }
}

// ---------------------------------------------------------------------------
// Skinny GEMM: C[64, M] += A[64, K] * W[M, K]^T     (split-K, atomic epilogue)
// block tile: 64 rows x 128 cols, 128 threads, 8x8 register tile, f32x2 FMAs
// ---------------------------------------------------------------------------
#define KT 16

__global__ void __launch_bounds__(128, 2) gemm_nt_kernel(
    const float* __restrict__ A, int lda, int reluA,
    const float* __restrict__ W,
    float* __restrict__ C, int M, int K, int KS) {
    __shared__ float As[KT][64];
    __shared__ float Ws[KT][128];

    int tid = threadIdx.x;
    int ty = tid >> 4;   // 0..7 : rows ty*8 .. ty*8+7
    int tx = tid & 15;   // 0..15: cols tx*8 .. tx*8+7
    int colBase = blockIdx.x * 128;
    int k0 = blockIdx.y * KS;
    int k1 = min(k0 + KS, K);

    ull acc[8][4];
#pragma unroll
    for (int r = 0; r < 8; r++)
#pragma unroll
        for (int j = 0; j < 4; j++) acc[r][j] = pk2(0.0f, 0.0f);

    for (int kb = k0; kb < k1; kb += KT) {
        // load A tile (64 x 16), stored transposed As[k][row]
#pragma unroll
        for (int it = 0; it < 2; it++) {
            int i = tid + it * 128;
            int row = i & 63;
            int q = i >> 6;          // 0..3 across the two iterations
            int kk = q * 4;
            int kg = kb + kk;
            float4 v = make_float4(0.f, 0.f, 0.f, 0.f);
            if (kg + 4 <= k1) {
                v = *(const float4*)(A + (size_t)row * lda + kg);
            } else {
                float tv[4] = {0.f, 0.f, 0.f, 0.f};
#pragma unroll
                for (int j = 0; j < 4; j++)
                    if (kg + j < k1) tv[j] = A[(size_t)row * lda + kg + j];
                v = make_float4(tv[0], tv[1], tv[2], tv[3]);
            }
            if (reluA) {
                v.x = fmaxf(v.x, 0.f); v.y = fmaxf(v.y, 0.f);
                v.z = fmaxf(v.z, 0.f); v.w = fmaxf(v.w, 0.f);
            }
            As[kk + 0][row] = v.x; As[kk + 1][row] = v.y;
            As[kk + 2][row] = v.z; As[kk + 3][row] = v.w;
        }
        // load W tile (128 x 16), stored transposed Ws[k][col]
#pragma unroll
        for (int it = 0; it < 4; it++) {
            int i = tid + it * 128;
            int col = i & 127;
            int q = i >> 7;          // 0..3
            int kk = q * 4;
            int kg = kb + kk;
            int gc = colBase + col;
            float4 v = make_float4(0.f, 0.f, 0.f, 0.f);
            if (gc < M) {
                if (kg + 4 <= k1) {
                    v = *(const float4*)(W + (size_t)gc * K + kg);
                } else {
                    float tv[4] = {0.f, 0.f, 0.f, 0.f};
#pragma unroll
                    for (int j = 0; j < 4; j++)
                        if (kg + j < k1) tv[j] = W[(size_t)gc * K + kg + j];
                    v = make_float4(tv[0], tv[1], tv[2], tv[3]);
                }
            }
            Ws[kk + 0][col] = v.x; Ws[kk + 1][col] = v.y;
            Ws[kk + 2][col] = v.z; Ws[kk + 3][col] = v.w;
        }
        __syncthreads();
#pragma unroll
        for (int kk = 0; kk < KT; kk++) {
            float4 a0 = *(const float4*)&As[kk][ty * 8];
            float4 a1 = *(const float4*)&As[kk][ty * 8 + 4];
            float4 b0 = *(const float4*)&Ws[kk][tx * 8];
            float4 b1 = *(const float4*)&Ws[kk][tx * 8 + 4];
            ull bp[4] = { pk2(b0.x, b0.y), pk2(b0.z, b0.w),
                          pk2(b1.x, b1.y), pk2(b1.z, b1.w) };
            float av[8] = {a0.x, a0.y, a0.z, a0.w, a1.x, a1.y, a1.z, a1.w};
#pragma unroll
            for (int r = 0; r < 8; r++) {
                ull ar = pk2(av[r], av[r]);
#pragma unroll
                for (int j = 0; j < 4; j++) ffma2(acc[r][j], ar, bp[j]);
            }
        }
        __syncthreads();
    }
#pragma unroll
    for (int r = 0; r < 8; r++) {
        int row = ty * 8 + r;
#pragma unroll
        for (int j = 0; j < 4; j++) {
            float lo, hi;
            upk2(acc[r][j], lo, hi);
            int col = colBase + tx * 8 + 2 * j;
            if (col < M)     atomicAdd(&C[(size_t)row * M + col], lo);
            if (col + 1 < M) atomicAdd(&C[(size_t)row * M + col + 1], hi);
        }
    }
}

// ---------------------------------------------------------------------------
// GRU combine: h = (1-z)*n + z*hprev   (gates gi/gh are bias-free partials)
// mode 1: also write h into dec_in second half
// mode 2: also write extra_out = extra_in + h  (residual adds)
// ---------------------------------------------------------------------------
__global__ void gru_combine_kernel(const float* __restrict__ gi,
                                   const float* __restrict__ gh,
                                   const float* __restrict__ bih,
                                   const float* __restrict__ bhh,
                                   const float* __restrict__ hprev,
                                   float* __restrict__ hout,
                                   const float* __restrict__ extra_in,
                                   float* __restrict__ extra_out,
                                   int mode) {
    int idx = blockIdx.x * 256 + threadIdx.x;
    if (idx >= NB * H2) return;
    int n = idx >> 10;
    int j = idx & (H2 - 1);
    const float* gin = gi + (size_t)n * H3;
    const float* ghn = gh + (size_t)n * H3;
    float ir = gin[j]          + bih[j];
    float iz = gin[j + H2]     + bih[j + H2];
    float in_ = gin[j + 2*H2]  + bih[j + 2*H2];
    float hr = ghn[j]          + bhh[j];
    float hz = ghn[j + H2]     + bhh[j + H2];
    float hn = ghn[j + 2*H2]   + bhh[j + 2*H2];
    float r = fast_sigmoid(ir + hr);
    float z = fast_sigmoid(iz + hz);
    float nn = fast_tanh(in_ + r * hn);
    float h = (1.0f - z) * nn + z * hprev[idx];
    hout[idx] = h;
    if (mode == 1) {
        extra_out[(size_t)n * H4 + H2 + j] = h;       // dec_in[:, 1024:2048]
    } else if (mode == 2) {
        extra_out[idx] = extra_in[idx] + h;           // residual accumulation
    }
}

// ---------------------------------------------------------------------------
// Attention pass 1: score[n,t] = exp( sum_h tanh(attW[n,t,h]+dp[n,h])*Wa[h] + b )
// masked to t < len(n). One warp per t, 8 t per block.
// ---------------------------------------------------------------------------
__global__ void __launch_bounds__(256) attn_score_kernel(
    const float* __restrict__ attW, const float* __restrict__ dp,
    const float* __restrict__ Wattn, const float* __restrict__ battn,
    const int* __restrict__ lengths, float* __restrict__ score) {
    __shared__ float dps[H2];
    __shared__ float was[H2];
    int n = blockIdx.y;
    for (int i = threadIdx.x; i < H2; i += 256) {
        dps[i] = dp[(size_t)n * H2 + i];
        was[i] = Wattn[i];
    }
    __syncthreads();
    int warp = threadIdx.x >> 5, lane = threadIdx.x & 31;
    int t = blockIdx.x * 8 + warp;
    if (t >= TT) return;
    int len = lengths[n];
    float s = 0.0f;
    if (t < len) {
        const float* row = attW + ((size_t)n * TT + t) * H2;
#pragma unroll 8
        for (int i = lane; i < H2; i += 32) {
            float e = fast_tanh(row[i] + dps[i]);
            s += e * was[i];
        }
#pragma unroll
        for (int o = 16; o; o >>= 1) s += __shfl_xor_sync(0xffffffffu, s, o);
        s = __expf(s + battn[0]);
    }
    if (lane == 0) score[(size_t)n * TT + t] = (t < len) ? s : 0.0f;
}

// ---------------------------------------------------------------------------
// Attention pass 2: winv[n] = 1 / max(sum_t score, 1e-12)
// ---------------------------------------------------------------------------
__global__ void attn_norm_kernel(const float* __restrict__ score,
                                 float* __restrict__ winv) {
    __shared__ float red[8];
    int n = blockIdx.x;
    float s = 0.0f;
    for (int t = threadIdx.x; t < TT; t += 256) s += score[(size_t)n * TT + t];
#pragma unroll
    for (int o = 16; o; o >>= 1) s += __shfl_xor_sync(0xffffffffu, s, o);
    if ((threadIdx.x & 31) == 0) red[threadIdx.x >> 5] = s;
    __syncthreads();
    if (threadIdx.x == 0) {
        float tot = 0.0f;
#pragma unroll
        for (int w = 0; w < 8; w++) tot += red[w];
        winv[n] = 1.0f / fmaxf(tot, 1e-12f);
    }
}

// ---------------------------------------------------------------------------
// Attention pass 3: dec_in[n, h] = (sum_t score[n,t]*enc[n,t,h]) * winv[n]
// grid (4, 64), 256 threads; 4 accumulators for MLP
// ---------------------------------------------------------------------------
__global__ void __launch_bounds__(256) attn_apply_kernel(
    const float* __restrict__ enc, const float* __restrict__ score,
    const float* __restrict__ winv, const int* __restrict__ lengths,
    float* __restrict__ dec_in) {
    __shared__ float ss[TT];
    int n = blockIdx.y;
    for (int i = threadIdx.x; i < TT; i += 256) ss[i] = score[(size_t)n * TT + i];
    __syncthreads();
    int h = blockIdx.x * 256 + threadIdx.x;
    int len = lengths[n];
    const float* e = enc + (size_t)n * TT * H2 + h;
    float a0 = 0.f, a1 = 0.f, a2 = 0.f, a3 = 0.f;
    int t = 0;
    for (; t + 8 <= len; t += 8) {
        a0 += ss[t + 0] * e[(size_t)(t + 0) * H2];
        a1 += ss[t + 1] * e[(size_t)(t + 1) * H2];
        a2 += ss[t + 2] * e[(size_t)(t + 2) * H2];
        a3 += ss[t + 3] * e[(size_t)(t + 3) * H2];
        a0 += ss[t + 4] * e[(size_t)(t + 4) * H2];
        a1 += ss[t + 5] * e[(size_t)(t + 5) * H2];
        a2 += ss[t + 6] * e[(size_t)(t + 6) * H2];
        a3 += ss[t + 7] * e[(size_t)(t + 7) * H2];
    }
    for (; t < len; t++) a0 += ss[t] * e[(size_t)t * H2];
    dec_in[(size_t)n * H4 + h] = (a0 + a1 + a2 + a3) * winv[n];
}

// ---------------------------------------------------------------------------
// Host launch
// ---------------------------------------------------------------------------
static inline void launch_gemm(const float* A, int lda, int reluA,
                               const float* W, float* C, int M, int K, int KS) {
    dim3 grid((M + 127) / 128, (K + KS - 1) / KS);
    gemm_nt_kernel<<<grid, 128>>>(A, lda, reluA, W, C, M, K, KS);
}

extern "C" void kernel_launch(void* const* d_in, const int* in_sizes, int n_in,
                              void* d_out, int out_size) {
    const float* input_enc   = (const float*)d_in[0];
    const float* attW_enc    = (const float*)d_in[1];
    const float* input_dec   = (const float*)d_in[2];
    const int*   lengths     = (const int*)  d_in[3];
    const float* hidden_att  = (const float*)d_in[4];
    const float* hidden_dec1 = (const float*)d_in[5];
    const float* hidden_dec2 = (const float*)d_in[6];
    const float* W_pre1 = (const float*)d_in[7];
    const float* b_pre1 = (const float*)d_in[8];
    const float* W_pre2 = (const float*)d_in[9];
    const float* b_pre2 = (const float*)d_in[10];
    const float* Wih_att = (const float*)d_in[11];
    const float* Whh_att = (const float*)d_in[12];
    const float* bih_att = (const float*)d_in[13];
    const float* bhh_att = (const float*)d_in[14];
    const float* W_ld  = (const float*)d_in[15];
    const float* b_ld  = (const float*)d_in[16];
    const float* W_attn = (const float*)d_in[17];
    const float* b_attn = (const float*)d_in[18];
    const float* W_sc  = (const float*)d_in[19];
    const float* b_sc  = (const float*)d_in[20];
    const float* Wih_d1 = (const float*)d_in[21];
    const float* Whh_d1 = (const float*)d_in[22];
    const float* bih_d1 = (const float*)d_in[23];
    const float* bhh_d1 = (const float*)d_in[24];
    const float* Wih_d2 = (const float*)d_in[25];
    const float* Whh_d2 = (const float*)d_in[26];
    const float* bih_d2 = (const float*)d_in[27];
    const float* bhh_d2 = (const float*)d_in[28];
    const float* W_out = (const float*)d_in[29];
    const float* b_out = (const float*)d_in[30];

    float* out = (float*)d_out;

    float* sc = nullptr;
    cudaGetSymbolAddress((void**)&sc, g_scratch);

    float* gi_att = sc + OFF_GI_ATT;
    float* gh_att = sc + OFF_GH_ATT;
    float* gi_d1  = sc + OFF_GI_D1;
    float* gh_d1  = sc + OFF_GH_D1;
    float* gi_d2  = sc + OFF_GI_D2;
    float* gh_d2  = sc + OFF_GH_D2;
    float* pre_a  = sc + OFF_PRE_A;
    float* pre    = sc + OFF_PRE;
    float* dp     = sc + OFF_DP;
    float* resid_sc = sc + OFF_RESID_SC;
    float* resid  = sc + OFF_RESID;
    float* resid2 = sc + OFF_RESID2;
    float* dec_in = sc + OFF_DECIN;
    float* score  = sc + OFF_SCORE;
    float* winv   = sc + OFF_WINV;

    // Output layout: [output(64*2*80) | h_att(64*1024) | h_dec1 | h_dec2]
    bool full_out = (out_size >= NB * RR * OO + 3 * NB * H2);
    float* h_att_out = full_out ? out + NB * RR * OO : sc + OFF_HATT;
    float* h_d1_out  = full_out ? h_att_out + NB * H2 : sc + OFF_HD1;
    float* h_d2_out  = full_out ? h_d1_out + NB * H2 : sc + OFF_HD2;

    // 0) zero gates + broadcast biases (output bias into d_out)
    init_kernel<<<(INIT_TOTAL + 255) / 256, 256>>>(out, b_pre1, b_pre2, b_ld, b_sc, b_out);

    // 1) prenet
    launch_gemm(input_dec, OO, 0, W_pre1, pre_a, H2, OO, 80);     // pre_a = x@W1^T + b1
    launch_gemm(pre_a, H2, 1, W_pre2, pre, HH, H2, 64);           // pre = relu(pre_a)@W2^T + b2

    // 2) attention GRU
    launch_gemm(pre, HH, 1, Wih_att, gi_att, H3, HH, 64);         // gi = relu(pre)@Wih^T
    launch_gemm(hidden_att, H2, 0, Whh_att, gh_att, H3, H2, 128); // gh = h@Whh^T
    gru_combine_kernel<<<(NB * H2 + 255) / 256, 256>>>(
        gi_att, gh_att, bih_att, bhh_att, hidden_att, h_att_out, nullptr, dec_in, 1);

    // 3) dec_proj = h_att @ W_ld^T + b_ld
    launch_gemm(h_att_out, H2, 0, W_ld, dp, H2, H2, 64);

    // 4) attention over T=800
    attn_score_kernel<<<dim3(TT / 8, NB), 256>>>(attW_enc, dp, W_attn, b_attn, lengths, score);
    attn_norm_kernel<<<NB, 256>>>(score, winv);
    attn_apply_kernel<<<dim3(H2 / 256, NB), 256>>>(input_enc, score, winv, lengths, dec_in);

    // 5) short-cut + decoder GRU 1
    launch_gemm(dec_in, H4, 0, W_sc, resid_sc, H2, H4, 128);      // residual = dec_in@W_sc^T + b_sc
    launch_gemm(dec_in, H4, 0, Wih_d1, gi_d1, H3, H4, 256);
    launch_gemm(hidden_dec1, H2, 0, Whh_d1, gh_d1, H3, H2, 128);
    gru_combine_kernel<<<(NB * H2 + 255) / 256, 256>>>(
        gi_d1, gh_d1, bih_d1, bhh_d1, hidden_dec1, h_d1_out, resid_sc, resid, 2);

    // 6) decoder GRU 2
    launch_gemm(resid, H2, 0, Wih_d2, gi_d2, H3, H2, 128);
    launch_gemm(hidden_dec2, H2, 0, Whh_d2, gh_d2, H3, H2, 128);
    gru_combine_kernel<<<(NB * H2 + 255) / 256, 256>>>(
        gi_d2, gh_d2, bih_d2, bhh_d2, hidden_dec2, h_d2_out, resid, resid2, 2);

    // 7) output projection (accumulates into bias-initialized d_out)
    launch_gemm(resid2, H2, 0, W_out, out, RR * OO, H2, 32);
}

// round 2
// speedup vs baseline: 1.4000x; 1.4000x over previous
#include <cuda_runtime.h>
#include <math.h>

// ---------------------------------------------------------------------------
// Problem constants
// ---------------------------------------------------------------------------
#define NB   64
#define TT   800
#define HH   512
#define H2   1024
#define H3   3072   // 3*H2
#define H4   2048   // 4*H
#define OO   80
#define RR   2

typedef unsigned long long ull;

// ---------------------------------------------------------------------------
// Scratch (single __device__ array; no allocations allowed)
// ---------------------------------------------------------------------------
#define GSZ       (NB * H3)            // 196608 per gate buffer
#define OFF_GI_ATT   0
#define OFF_GH_ATT   (1 * GSZ)
#define OFF_GI_D1    (2 * GSZ)
#define OFF_GH_D1    (3 * GSZ)
#define OFF_GI_D2    (4 * GSZ)
#define OFF_GH_D2    (5 * GSZ)
#define OFF_PRE_A    (6 * GSZ)                         // 64x1024
#define OFF_PRE      (OFF_PRE_A   + NB * H2)           // 64x512
#define OFF_DP       (OFF_PRE     + NB * HH)           // 64x1024
#define OFF_RESID_SC (OFF_DP      + NB * H2)           // 64x1024
#define OFF_RESID    (OFF_RESID_SC+ NB * H2)           // 64x1024
#define OFF_RESID2   (OFF_RESID   + NB * H2)           // 64x1024
#define OFF_DECIN    (OFF_RESID2  + NB * H2)           // 64x2048
#define OFF_SCORE    (OFF_DECIN   + NB * H4)           // 64x800
#define OFF_HATT     (OFF_SCORE   + NB * TT)           // fallback h outputs
#define OFF_HD1      (OFF_HATT    + NB * H2)
#define OFF_HD2      (OFF_HD1     + NB * H2)
#define SCRATCH_TOTAL (OFF_HD2    + NB * H2)

__device__ float g_scratch[SCRATCH_TOTAL];

// ---------------------------------------------------------------------------
// Math helpers
// ---------------------------------------------------------------------------
__device__ __forceinline__ float fast_tanh(float x) {
    float e = __expf(2.0f * x);
    return 1.0f - 2.0f / (e + 1.0f);
}
__device__ __forceinline__ float fast_sigmoid(float x) {
    return 1.0f / (1.0f + __expf(-x));
}

__device__ __forceinline__ ull pk2(float x, float y) {
    ull r;
    asm("mov.b64 %0, {%1, %2};" : "=l"(r) : "f"(x), "f"(y));
    return r;
}
__device__ __forceinline__ void upk2(ull v, float& x, float& y) {
    asm("mov.b64 {%0, %1}, %2;" : "=f"(x), "=f"(y) : "l"(v));
}
__device__ __forceinline__ void ffma2(ull& d, ull a, ull b) {
    asm("fma.rn.f32x2 %0, %1, %2, %0;" : "+l"(d) : "l"(a), "l"(b));
}

// ---------------------------------------------------------------------------
// Init: zero gate buffers, broadcast biases into atomically-accumulated outputs
// ---------------------------------------------------------------------------
#define INIT_TOTAL (6 * GSZ + NB * H2 + NB * HH + NB * H2 + NB * H2 + NB * RR * OO)

__global__ void init_kernel(float* __restrict__ out,
                            const float* __restrict__ b_pre1,
                            const float* __restrict__ b_pre2,
                            const float* __restrict__ b_ld,
                            const float* __restrict__ b_sc,
                            const float* __restrict__ b_out) {
    int idx = blockIdx.x * 256 + threadIdx.x;
    if (idx < 6 * GSZ) { g_scratch[idx] = 0.0f; return; }
    idx -= 6 * GSZ;
    if (idx < NB * H2) { g_scratch[OFF_PRE_A + idx] = b_pre1[idx & (H2 - 1)]; return; }
    idx -= NB * H2;
    if (idx < NB * HH) { g_scratch[OFF_PRE + idx] = b_pre2[idx & (HH - 1)]; return; }
    idx -= NB * HH;
    if (idx < NB * H2) { g_scratch[OFF_DP + idx] = b_ld[idx & (H2 - 1)]; return; }
    idx -= NB * H2;
    if (idx < NB * H2) { g_scratch[OFF_RESID_SC + idx] = b_sc[idx & (H2 - 1)]; return; }
    idx -= NB * H2;
    if (idx < NB * RR * OO) { out[idx] = b_out[idx % (RR * OO)]; return; }
}

// ---------------------------------------------------------------------------
// Batched skinny GEMM: for each descriptor, C[64, M] += A[64, K] * W[M, K]^T
// Per-CTA tile: 64 rows x 128 cols, 256 threads, 8x4 per-thread, f32x2 FMAs,
// split-K with atomic epilogue.  Requires: K % KS == 0, KS % 16 == 0, lda ok.
// ---------------------------------------------------------------------------
#define KT 16

struct GD {
    const float* A;
    const float* W;
    float* C;
    int lda, M, K, KS, reluA, nCol, start, nBlocks;
};
struct GemmBatch { GD d[4]; int n; };

__global__ void __launch_bounds__(256, 3) multi_gemm_kernel(GemmBatch P) {
    __shared__ float As[KT][64];
    __shared__ float Ws[KT][128];

    int b = blockIdx.x;
    GD d = P.d[0];
#pragma unroll
    for (int i = 1; i < 4; i++) {
        if (i < P.n && b >= P.d[i].start) d = P.d[i];
    }
    int lb = b - d.start;
    int colBlock = lb % d.nCol;
    int kBlock = lb / d.nCol;
    int colBase = colBlock * 128;
    int k0 = kBlock * d.KS;
    int k1 = min(k0 + d.KS, d.K);

    int tid = threadIdx.x;
    int ty = tid >> 5;   // 0..7 : rows ty*8 .. ty*8+7
    int tx = tid & 31;   // 0..31: cols tx*4 .. tx*4+3

    ull acc[8][2];
#pragma unroll
    for (int r = 0; r < 8; r++) {
        acc[r][0] = pk2(0.0f, 0.0f);
        acc[r][1] = pk2(0.0f, 0.0f);
    }

    // A-load indices (constant across kb)
    int arow = tid & 63;
    int akk  = (tid >> 6) << 2;       // 0,4,8,12

    for (int kb = k0; kb < k1; kb += KT) {
        // A tile: 64 x 16
        {
            float4 v = *(const float4*)(d.A + (size_t)arow * d.lda + kb + akk);
            if (d.reluA) {
                v.x = fmaxf(v.x, 0.f); v.y = fmaxf(v.y, 0.f);
                v.z = fmaxf(v.z, 0.f); v.w = fmaxf(v.w, 0.f);
            }
            As[akk + 0][arow] = v.x; As[akk + 1][arow] = v.y;
            As[akk + 2][arow] = v.z; As[akk + 3][arow] = v.w;
        }
        // W tile: 128 x 16
#pragma unroll
        for (int it = 0; it < 2; it++) {
            int i = tid + it * 256;
            int col = i & 127;
            int kk = (i >> 7) << 2;
            int gc = colBase + col;
            float4 v = make_float4(0.f, 0.f, 0.f, 0.f);
            if (gc < d.M) v = *(const float4*)(d.W + (size_t)gc * d.K + kb + kk);
            Ws[kk + 0][col] = v.x; Ws[kk + 1][col] = v.y;
            Ws[kk + 2][col] = v.z; Ws[kk + 3][col] = v.w;
        }
        __syncthreads();
#pragma unroll
        for (int kk = 0; kk < KT; kk++) {
            float4 a0 = *(const float4*)&As[kk][ty * 8];
            float4 a1 = *(const float4*)&As[kk][ty * 8 + 4];
            float4 bv = *(const float4*)&Ws[kk][tx * 4];
            ull bp0 = pk2(bv.x, bv.y);
            ull bp1 = pk2(bv.z, bv.w);
            float av[8] = {a0.x, a0.y, a0.z, a0.w, a1.x, a1.y, a1.z, a1.w};
#pragma unroll
            for (int r = 0; r < 8; r++) {
                ull ar = pk2(av[r], av[r]);
                ffma2(acc[r][0], ar, bp0);
                ffma2(acc[r][1], ar, bp1);
            }
        }
        __syncthreads();
    }
#pragma unroll
    for (int r = 0; r < 8; r++) {
        int row = ty * 8 + r;
#pragma unroll
        for (int j = 0; j < 2; j++) {
            float lo, hi;
            upk2(acc[r][j], lo, hi);
            int col = colBase + tx * 4 + 2 * j;
            if (col < d.M)     atomicAdd(&d.C[(size_t)row * d.M + col], lo);
            if (col + 1 < d.M) atomicAdd(&d.C[(size_t)row * d.M + col + 1], hi);
        }
    }
}

// ---------------------------------------------------------------------------
// GRU combine: h = (1-z)*n + z*hprev   (gates gi/gh are bias-free partials)
// mode 1: also write h into dec_in second half
// mode 2: also write extra_out = extra_in + h  (residual adds)
// ---------------------------------------------------------------------------
__global__ void gru_combine_kernel(const float* __restrict__ gi,
                                   const float* __restrict__ gh,
                                   const float* __restrict__ bih,
                                   const float* __restrict__ bhh,
                                   const float* __restrict__ hprev,
                                   float* __restrict__ hout,
                                   const float* __restrict__ extra_in,
                                   float* __restrict__ extra_out,
                                   int mode) {
    int idx = blockIdx.x * 256 + threadIdx.x;
    if (idx >= NB * H2) return;
    int n = idx >> 10;
    int j = idx & (H2 - 1);
    const float* gin = gi + (size_t)n * H3;
    const float* ghn = gh + (size_t)n * H3;
    float ir = gin[j]          + bih[j];
    float iz = gin[j + H2]     + bih[j + H2];
    float in_ = gin[j + 2*H2]  + bih[j + 2*H2];
    float hr = ghn[j]          + bhh[j];
    float hz = ghn[j + H2]     + bhh[j + H2];
    float hn = ghn[j + 2*H2]   + bhh[j + 2*H2];
    float r = fast_sigmoid(ir + hr);
    float z = fast_sigmoid(iz + hz);
    float nn = fast_tanh(in_ + r * hn);
    float h = (1.0f - z) * nn + z * hprev[idx];
    hout[idx] = h;
    if (mode == 1) {
        extra_out[(size_t)n * H4 + H2 + j] = h;       // dec_in[:, 1024:2048]
    } else if (mode == 2) {
        extra_out[idx] = extra_in[idx] + h;           // residual accumulation
    }
}

// ---------------------------------------------------------------------------
// Attention pass 1: score[n,t] = exp( sum_h tanh(attW[n,t,h]+dp[n,h])*Wa[h] + b )
// masked to t < len(n). One warp per t, 8 t per block.
// ---------------------------------------------------------------------------
__global__ void __launch_bounds__(256) attn_score_kernel(
    const float* __restrict__ attW, const float* __restrict__ dp,
    const float* __restrict__ Wattn, const float* __restrict__ battn,
    const int* __restrict__ lengths, float* __restrict__ score) {
    __shared__ float dps[H2];
    __shared__ float was[H2];
    int n = blockIdx.y;
    for (int i = threadIdx.x; i < H2; i += 256) {
        dps[i] = dp[(size_t)n * H2 + i];
        was[i] = Wattn[i];
    }
    __syncthreads();
    int warp = threadIdx.x >> 5, lane = threadIdx.x & 31;
    int t = blockIdx.x * 8 + warp;
    if (t >= TT) return;
    int len = lengths[n];
    float s = 0.0f;
    if (t < len) {
        const float* row = attW + ((size_t)n * TT + t) * H2;
#pragma unroll 8
        for (int i = lane; i < H2; i += 32) {
            float e = fast_tanh(row[i] + dps[i]);
            s += e * was[i];
        }
#pragma unroll
        for (int o = 16; o; o >>= 1) s += __shfl_xor_sync(0xffffffffu, s, o);
        s = __expf(s + battn[0]);
    }
    if (lane == 0) score[(size_t)n * TT + t] = (t < len) ? s : 0.0f;
}

// ---------------------------------------------------------------------------
// Attention pass 2 (fused norm + apply):
//   winv = 1/max(sum_t score,1e-12); dec_in[n,h] = winv * sum_t score*enc[n,t,h]
// ---------------------------------------------------------------------------
__global__ void __launch_bounds__(256) attn_apply_kernel(
    const float* __restrict__ enc, const float* __restrict__ score,
    const int* __restrict__ lengths, float* __restrict__ dec_in) {
    __shared__ float ss[TT];
    __shared__ float red[8];
    __shared__ float winv_s;
    int n = blockIdx.y;
    int tid = threadIdx.x;
    float psum = 0.0f;
    for (int i = tid; i < TT; i += 256) {
        float v = score[(size_t)n * TT + i];
        ss[i] = v;
        psum += v;
    }
#pragma unroll
    for (int o = 16; o; o >>= 1) psum += __shfl_xor_sync(0xffffffffu, psum, o);
    if ((tid & 31) == 0) red[tid >> 5] = psum;
    __syncthreads();
    if (tid == 0) {
        float tot = 0.0f;
#pragma unroll
        for (int w = 0; w < 8; w++) tot += red[w];
        winv_s = 1.0f / fmaxf(tot, 1e-12f);
    }
    __syncthreads();
    int h = blockIdx.x * 256 + tid;
    int len = lengths[n];
    const float* e = enc + (size_t)n * TT * H2 + h;
    float a0 = 0.f, a1 = 0.f, a2 = 0.f, a3 = 0.f;
    int t = 0;
    for (; t + 8 <= len; t += 8) {
        a0 += ss[t + 0] * e[(size_t)(t + 0) * H2];
        a1 += ss[t + 1] * e[(size_t)(t + 1) * H2];
        a2 += ss[t + 2] * e[(size_t)(t + 2) * H2];
        a3 += ss[t + 3] * e[(size_t)(t + 3) * H2];
        a0 += ss[t + 4] * e[(size_t)(t + 4) * H2];
        a1 += ss[t + 5] * e[(size_t)(t + 5) * H2];
        a2 += ss[t + 6] * e[(size_t)(t + 6) * H2];
        a3 += ss[t + 7] * e[(size_t)(t + 7) * H2];
    }
    for (; t < len; t++) a0 += ss[t] * e[(size_t)t * H2];
    dec_in[(size_t)n * H4 + h] = (a0 + a1 + a2 + a3) * winv_s;
}

// ---------------------------------------------------------------------------
// Host launch
// ---------------------------------------------------------------------------
static inline GD make_gd(const float* A, int lda, int reluA, const float* W,
                         float* C, int M, int K, int KS, int start) {
    GD d;
    d.A = A; d.W = W; d.C = C;
    d.lda = lda; d.M = M; d.K = K; d.KS = KS; d.reluA = reluA;
    d.nCol = (M + 127) / 128;
    d.start = start;
    d.nBlocks = d.nCol * ((K + KS - 1) / KS);
    return d;
}

static inline void launch_batch(GD* ds, int n) {
    GemmBatch P;
    int start = 0;
    for (int i = 0; i < n; i++) {
        ds[i].start = start;
        start += ds[i].nBlocks;
        P.d[i] = ds[i];
    }
    for (int i = n; i < 4; i++) P.d[i] = P.d[n - 1];
    P.n = n;
    multi_gemm_kernel<<<start, 256>>>(P);
}

extern "C" void kernel_launch(void* const* d_in, const int* in_sizes, int n_in,
                              void* d_out, int out_size) {
    const float* input_enc   = (const float*)d_in[0];
    const float* attW_enc    = (const float*)d_in[1];
    const float* input_dec   = (const float*)d_in[2];
    const int*   lengths     = (const int*)  d_in[3];
    const float* hidden_att  = (const float*)d_in[4];
    const float* hidden_dec1 = (const float*)d_in[5];
    const float* hidden_dec2 = (const float*)d_in[6];
    const float* W_pre1 = (const float*)d_in[7];
    const float* b_pre1 = (const float*)d_in[8];
    const float* W_pre2 = (const float*)d_in[9];
    const float* b_pre2 = (const float*)d_in[10];
    const float* Wih_att = (const float*)d_in[11];
    const float* Whh_att = (const float*)d_in[12];
    const float* bih_att = (const float*)d_in[13];
    const float* bhh_att = (const float*)d_in[14];
    const float* W_ld  = (const float*)d_in[15];
    const float* b_ld  = (const float*)d_in[16];
    const float* W_attn = (const float*)d_in[17];
    const float* b_attn = (const float*)d_in[18];
    const float* W_sc  = (const float*)d_in[19];
    const float* b_sc  = (const float*)d_in[20];
    const float* Wih_d1 = (const float*)d_in[21];
    const float* Whh_d1 = (const float*)d_in[22];
    const float* bih_d1 = (const float*)d_in[23];
    const float* bhh_d1 = (const float*)d_in[24];
    const float* Wih_d2 = (const float*)d_in[25];
    const float* Whh_d2 = (const float*)d_in[26];
    const float* bih_d2 = (const float*)d_in[27];
    const float* bhh_d2 = (const float*)d_in[28];
    const float* W_out = (const float*)d_in[29];
    const float* b_out = (const float*)d_in[30];

    float* out = (float*)d_out;

    float* sc = nullptr;
    cudaGetSymbolAddress((void**)&sc, g_scratch);

    float* gi_att = sc + OFF_GI_ATT;
    float* gh_att = sc + OFF_GH_ATT;
    float* gi_d1  = sc + OFF_GI_D1;
    float* gh_d1  = sc + OFF_GH_D1;
    float* gi_d2  = sc + OFF_GI_D2;
    float* gh_d2  = sc + OFF_GH_D2;
    float* pre_a  = sc + OFF_PRE_A;
    float* pre    = sc + OFF_PRE;
    float* dp     = sc + OFF_DP;
    float* resid_sc = sc + OFF_RESID_SC;
    float* resid  = sc + OFF_RESID;
    float* resid2 = sc + OFF_RESID2;
    float* dec_in = sc + OFF_DECIN;
    float* score  = sc + OFF_SCORE;

    // Output layout: [output(64*2*80) | h_att(64*1024) | h_dec1 | h_dec2]
    bool full_out = (out_size >= NB * RR * OO + 3 * NB * H2);
    float* h_att_out = full_out ? out + NB * RR * OO : sc + OFF_HATT;
    float* h_d1_out  = full_out ? h_att_out + NB * H2 : sc + OFF_HD1;
    float* h_d2_out  = full_out ? h_d1_out + NB * H2 : sc + OFF_HD2;

    // 0) zero gates + broadcast biases (output bias into d_out)
    init_kernel<<<(INIT_TOTAL + 255) / 256, 256>>>(out, b_pre1, b_pre2, b_ld, b_sc, b_out);

    // 1) stage A: everything that depends only on inputs
    {
        GD ds[4] = {
            make_gd(input_dec,   OO, 0, W_pre1,  pre_a, H2, OO,   16, 0),
            make_gd(hidden_att,  H2, 0, Whh_att, gh_att, H3, H2,  128, 0),
            make_gd(hidden_dec1, H2, 0, Whh_d1,  gh_d1,  H3, H2,  128, 0),
            make_gd(hidden_dec2, H2, 0, Whh_d2,  gh_d2,  H3, H2,  128, 0),
        };
        launch_batch(ds, 4);
    }
    // 2) pre = relu(pre_a) @ W_pre2^T + b2
    {
        GD ds[1] = { make_gd(pre_a, H2, 1, W_pre2, pre, HH, H2, 32, 0) };
        launch_batch(ds, 1);
    }
    // 3) gi_att = relu(pre) @ Wih_att^T
    {
        GD ds[1] = { make_gd(pre, HH, 1, Wih_att, gi_att, H3, HH, 32, 0) };
        launch_batch(ds, 1);
    }
    // 4) h_att
    gru_combine_kernel<<<(NB * H2 + 255) / 256, 256>>>(
        gi_att, gh_att, bih_att, bhh_att, hidden_att, h_att_out, nullptr, dec_in, 1);
    // 5) dec_proj
    {
        GD ds[1] = { make_gd(h_att_out, H2, 0, W_ld, dp, H2, H2, 32, 0) };
        launch_batch(ds, 1);
    }
    // 6) attention
    attn_score_kernel<<<dim3(TT / 8, NB), 256>>>(attW_enc, dp, W_attn, b_attn, lengths, score);
    attn_apply_kernel<<<dim3(H2 / 256, NB), 256>>>(input_enc, score, lengths, dec_in);
    // 7) short-cut + decoder GRU 1 input gates (both consume dec_in)
    {
        GD ds[2] = {
            make_gd(dec_in, H4, 0, W_sc,   resid_sc, H2, H4, 128, 0),
            make_gd(dec_in, H4, 0, Wih_d1, gi_d1,    H3, H4, 128, 0),
        };
        launch_batch(ds, 2);
    }
    gru_combine_kernel<<<(NB * H2 + 255) / 256, 256>>>(
        gi_d1, gh_d1, bih_d1, bhh_d1, hidden_dec1, h_d1_out, resid_sc, resid, 2);
    // 8) decoder GRU 2
    {
        GD ds[1] = { make_gd(resid, H2, 0, Wih_d2, gi_d2, H3, H2, 64, 0) };
        launch_batch(ds, 1);
    }
    gru_combine_kernel<<<(NB * H2 + 255) / 256, 256>>>(
        gi_d2, gh_d2, bih_d2, bhh_d2, hidden_dec2, h_d2_out, resid, resid2, 2);
    // 9) output projection
    {
        GD ds[1] = { make_gd(resid2, H2, 0, W_out, out, RR * OO, H2, 16, 0) };
        launch_batch(ds, 1);
    }
}

// round 3
// speedup vs baseline: 1.7901x; 1.2786x over previous
#include <cuda_runtime.h>
#include <math.h>

// ---------------------------------------------------------------------------
// Problem constants
// ---------------------------------------------------------------------------
#define NB   64
#define TT   800
#define HH   512
#define H2   1024
#define H3   3072   // 3*H2
#define H4   2048   // 4*H
#define OO   80
#define RR   2

typedef unsigned long long ull;

// ---------------------------------------------------------------------------
// Scratch
// ---------------------------------------------------------------------------
#define GSZ       (NB * H3)
#define OFF_GI_ATT   0
#define OFF_GH_ATT   (1 * GSZ)
#define OFF_GI_D1    (2 * GSZ)
#define OFF_GH_D1    (3 * GSZ)
#define OFF_GI_D2    (4 * GSZ)
#define OFF_GH_D2    (5 * GSZ)
#define OFF_PRE_A    (6 * GSZ)
#define OFF_PRE      (OFF_PRE_A   + NB * H2)
#define OFF_DP       (OFF_PRE     + NB * HH)
#define OFF_RESID_SC (OFF_DP      + NB * H2)
#define OFF_RESID    (OFF_RESID_SC+ NB * H2)
#define OFF_RESID2   (OFF_RESID   + NB * H2)
#define OFF_DECIN    (OFF_RESID2  + NB * H2)
#define OFF_SCORE    (OFF_DECIN   + NB * H4)
#define OFF_HATT     (OFF_SCORE   + NB * TT)
#define OFF_HD1      (OFF_HATT    + NB * H2)
#define OFF_HD2      (OFF_HD1     + NB * H2)
#define SCRATCH_TOTAL (OFF_HD2    + NB * H2)

__device__ float g_scratch[SCRATCH_TOTAL];

// ---------------------------------------------------------------------------
// Math helpers
// ---------------------------------------------------------------------------
__device__ __forceinline__ float fast_tanh(float x) {
    float e = __expf(2.0f * x);
    return 1.0f - 2.0f / (e + 1.0f);
}
__device__ __forceinline__ float approx_tanh(float x) {
    float y;
    asm("tanh.approx.f32 %0, %1;" : "=f"(y) : "f"(x));
    return y;
}
__device__ __forceinline__ float fast_sigmoid(float x) {
    return 1.0f / (1.0f + __expf(-x));
}

__device__ __forceinline__ ull pk2(float x, float y) {
    ull r;
    asm("mov.b64 %0, {%1, %2};" : "=l"(r) : "f"(x), "f"(y));
    return r;
}
__device__ __forceinline__ void upk2(ull v, float& x, float& y) {
    asm("mov.b64 {%0, %1}, %2;" : "=f"(x), "=f"(y) : "l"(v));
}
__device__ __forceinline__ void ffma2(ull& d, ull a, ull b) {
    asm("fma.rn.f32x2 %0, %1, %2, %0;" : "+l"(d) : "l"(a), "l"(b));
}
__device__ __forceinline__ void red4(float* p, float x, float y, float z, float w) {
    asm volatile("red.global.add.v4.f32 [%0], {%1,%2,%3,%4};"
                 :: "l"(p), "f"(x), "f"(y), "f"(z), "f"(w) : "memory");
}

// ---------------------------------------------------------------------------
// Init: zero gate buffers, broadcast biases
// ---------------------------------------------------------------------------
#define INIT_TOTAL (6 * GSZ + NB * H2 + NB * HH + NB * H2 + NB * H2 + NB * RR * OO)

__global__ void init_kernel(float* __restrict__ out,
                            const float* __restrict__ b_pre1,
                            const float* __restrict__ b_pre2,
                            const float* __restrict__ b_ld,
                            const float* __restrict__ b_sc,
                            const float* __restrict__ b_out) {
    int idx = blockIdx.x * 256 + threadIdx.x;
    if (idx < 6 * GSZ) { g_scratch[idx] = 0.0f; return; }
    idx -= 6 * GSZ;
    if (idx < NB * H2) { g_scratch[OFF_PRE_A + idx] = b_pre1[idx & (H2 - 1)]; return; }
    idx -= NB * H2;
    if (idx < NB * HH) { g_scratch[OFF_PRE + idx] = b_pre2[idx & (HH - 1)]; return; }
    idx -= NB * HH;
    if (idx < NB * H2) { g_scratch[OFF_DP + idx] = b_ld[idx & (H2 - 1)]; return; }
    idx -= NB * H2;
    if (idx < NB * H2) { g_scratch[OFF_RESID_SC + idx] = b_sc[idx & (H2 - 1)]; return; }
    idx -= NB * H2;
    if (idx < NB * RR * OO) { out[idx] = b_out[idx % (RR * OO)]; return; }
}

// ---------------------------------------------------------------------------
// Batched skinny GEMM: C[64, M] += A[64, K] * W[M, K]^T
// 64x128 tile, 256 threads, 8x4 per thread, f32x2 FMAs, split-K,
// register-staged double-buffered smem, red.v4 epilogue.
// ---------------------------------------------------------------------------
#define KT 16

struct GD {
    const float* A;
    const float* W;
    float* C;
    int lda, M, K, KS, reluA, nCol, start, nBlocks;
};
struct GemmBatch { GD d[4]; int n; };

__global__ void __launch_bounds__(256, 3) multi_gemm_kernel(GemmBatch P) {
    __shared__ float As[2][KT][64];
    __shared__ float Ws[2][KT][128];

    int b = blockIdx.x;
    GD d = P.d[0];
#pragma unroll
    for (int i = 1; i < 4; i++) {
        if (i < P.n && b >= P.d[i].start) d = P.d[i];
    }
    int lb = b - d.start;
    int colBlock = lb % d.nCol;
    int kBlock = lb / d.nCol;
    int colBase = colBlock * 128;
    int k0 = kBlock * d.KS;
    int k1 = min(k0 + d.KS, d.K);

    int tid = threadIdx.x;
    int ty = tid >> 5;
    int tx = tid & 31;

    int arow = tid & 63;
    int akk  = (tid >> 6) << 2;          // 0,4,8,12
    int wcol = tid & 127;
    int wkk  = (tid >> 7) << 2;          // 0,4
    int gc = colBase + wcol;
    bool wvalid = (gc < d.M);

    const float* aptr = d.A + (size_t)arow * d.lda + akk;
    const float* wptr = d.W + (size_t)gc * d.K + wkk;

    ull acc[8][2];
#pragma unroll
    for (int r = 0; r < 8; r++) {
        acc[r][0] = pk2(0.0f, 0.0f);
        acc[r][1] = pk2(0.0f, 0.0f);
    }

    float4 areg, wreg0, wreg1;
    const float4 z4 = make_float4(0.f, 0.f, 0.f, 0.f);

    // prologue: load + store first tile
    areg = *(const float4*)(aptr + k0);
    if (d.reluA) {
        areg.x = fmaxf(areg.x, 0.f); areg.y = fmaxf(areg.y, 0.f);
        areg.z = fmaxf(areg.z, 0.f); areg.w = fmaxf(areg.w, 0.f);
    }
    wreg0 = wvalid ? *(const float4*)(wptr + k0) : z4;
    wreg1 = wvalid ? *(const float4*)(wptr + k0 + 8) : z4;

    As[0][akk + 0][arow] = areg.x; As[0][akk + 1][arow] = areg.y;
    As[0][akk + 2][arow] = areg.z; As[0][akk + 3][arow] = areg.w;
    Ws[0][wkk + 0][wcol] = wreg0.x; Ws[0][wkk + 1][wcol] = wreg0.y;
    Ws[0][wkk + 2][wcol] = wreg0.z; Ws[0][wkk + 3][wcol] = wreg0.w;
    Ws[0][wkk + 8][wcol] = wreg1.x; Ws[0][wkk + 9][wcol] = wreg1.y;
    Ws[0][wkk +10][wcol] = wreg1.z; Ws[0][wkk +11][wcol] = wreg1.w;
    __syncthreads();

    int buf = 0;
    for (int kb = k0; kb < k1; kb += KT) {
        bool nxt = (kb + KT) < k1;
        if (nxt) {
            int kn = kb + KT;
            areg = *(const float4*)(aptr + kn);
            if (d.reluA) {
                areg.x = fmaxf(areg.x, 0.f); areg.y = fmaxf(areg.y, 0.f);
                areg.z = fmaxf(areg.z, 0.f); areg.w = fmaxf(areg.w, 0.f);
            }
            wreg0 = wvalid ? *(const float4*)(wptr + kn) : z4;
            wreg1 = wvalid ? *(const float4*)(wptr + kn + 8) : z4;
        }
#pragma unroll
        for (int kk = 0; kk < KT; kk++) {
            float4 a0 = *(const float4*)&As[buf][kk][ty * 8];
            float4 a1 = *(const float4*)&As[buf][kk][ty * 8 + 4];
            float4 bv = *(const float4*)&Ws[buf][kk][tx * 4];
            ull bp0 = pk2(bv.x, bv.y);
            ull bp1 = pk2(bv.z, bv.w);
            float av[8] = {a0.x, a0.y, a0.z, a0.w, a1.x, a1.y, a1.z, a1.w};
#pragma unroll
            for (int r = 0; r < 8; r++) {
                ull ar = pk2(av[r], av[r]);
                ffma2(acc[r][0], ar, bp0);
                ffma2(acc[r][1], ar, bp1);
            }
        }
        if (nxt) {
            int nb = buf ^ 1;
            As[nb][akk + 0][arow] = areg.x; As[nb][akk + 1][arow] = areg.y;
            As[nb][akk + 2][arow] = areg.z; As[nb][akk + 3][arow] = areg.w;
            Ws[nb][wkk + 0][wcol] = wreg0.x; Ws[nb][wkk + 1][wcol] = wreg0.y;
            Ws[nb][wkk + 2][wcol] = wreg0.z; Ws[nb][wkk + 3][wcol] = wreg0.w;
            Ws[nb][wkk + 8][wcol] = wreg1.x; Ws[nb][wkk + 9][wcol] = wreg1.y;
            Ws[nb][wkk +10][wcol] = wreg1.z; Ws[nb][wkk +11][wcol] = wreg1.w;
        }
        __syncthreads();
        buf ^= 1;
    }

#pragma unroll
    for (int r = 0; r < 8; r++) {
        int row = ty * 8 + r;
        int col = colBase + tx * 4;
        if (col < d.M) {
            float x, y, z, w;
            upk2(acc[r][0], x, y);
            upk2(acc[r][1], z, w);
            red4(&d.C[(size_t)row * d.M + col], x, y, z, w);
        }
    }
}

// ---------------------------------------------------------------------------
// GRU combine
// ---------------------------------------------------------------------------
__global__ void gru_combine_kernel(const float* __restrict__ gi,
                                   const float* __restrict__ gh,
                                   const float* __restrict__ bih,
                                   const float* __restrict__ bhh,
                                   const float* __restrict__ hprev,
                                   float* __restrict__ hout,
                                   const float* __restrict__ extra_in,
                                   float* __restrict__ extra_out,
                                   int mode) {
    int idx = blockIdx.x * 256 + threadIdx.x;
    if (idx >= NB * H2) return;
    int n = idx >> 10;
    int j = idx & (H2 - 1);
    const float* gin = gi + (size_t)n * H3;
    const float* ghn = gh + (size_t)n * H3;
    float ir = gin[j]          + bih[j];
    float iz = gin[j + H2]     + bih[j + H2];
    float in_ = gin[j + 2*H2]  + bih[j + 2*H2];
    float hr = ghn[j]          + bhh[j];
    float hz = ghn[j + H2]     + bhh[j + H2];
    float hn = ghn[j + 2*H2]   + bhh[j + 2*H2];
    float r = fast_sigmoid(ir + hr);
    float z = fast_sigmoid(iz + hz);
    float nn = fast_tanh(in_ + r * hn);
    float h = (1.0f - z) * nn + z * hprev[idx];
    hout[idx] = h;
    if (mode == 1) {
        extra_out[(size_t)n * H4 + H2 + j] = h;
    } else if (mode == 2) {
        extra_out[idx] = extra_in[idx] + h;
    }
}

// ---------------------------------------------------------------------------
// Attention pass 1: score + zero dec_in attention half
// ---------------------------------------------------------------------------
__global__ void __launch_bounds__(256) attn_score_kernel(
    const float* __restrict__ attW, const float* __restrict__ dp,
    const float* __restrict__ Wattn, const float* __restrict__ battn,
    const int* __restrict__ lengths, float* __restrict__ score,
    float* __restrict__ dec_in) {
    __shared__ float dps[H2];
    __shared__ float was[H2];
    int n = blockIdx.y;
    // zero dec_in[:, 0:1024] (safe: apply runs in a later launch)
    if (blockIdx.x < 16 && threadIdx.x < 64) {
        dec_in[(size_t)n * H4 + blockIdx.x * 64 + threadIdx.x] = 0.0f;
    }
    for (int i = threadIdx.x; i < H2; i += 256) {
        dps[i] = dp[(size_t)n * H2 + i];
        was[i] = Wattn[i];
    }
    __syncthreads();
    int warp = threadIdx.x >> 5, lane = threadIdx.x & 31;
    int t = blockIdx.x * 8 + warp;
    if (t >= TT) return;
    int len = lengths[n];
    float s = 0.0f;
    if (t < len) {
        const float* row = attW + ((size_t)n * TT + t) * H2;
#pragma unroll 8
        for (int i = lane; i < H2; i += 32) {
            float e = approx_tanh(row[i] + dps[i]);
            s += e * was[i];
        }
#pragma unroll
        for (int o = 16; o; o >>= 1) s += __shfl_xor_sync(0xffffffffu, s, o);
        s = __expf(s + battn[0]);
    }
    if (lane == 0) score[(size_t)n * TT + t] = (t < len) ? s : 0.0f;
}

// ---------------------------------------------------------------------------
// Attention pass 2 (t-split, fused norm): atomicAdd partial weighted sums
// ---------------------------------------------------------------------------
#define TSPLIT 4
#define TCH (TT / TSPLIT)   // 200

__global__ void __launch_bounds__(256) attn_apply_kernel(
    const float* __restrict__ enc, const float* __restrict__ score,
    float* __restrict__ dec_in) {
    __shared__ float ss[TCH];
    __shared__ float red_[8];
    __shared__ float winv_s;
    int n = blockIdx.y;
    int t0 = blockIdx.z * TCH;
    int tid = threadIdx.x;
    const float* srow = score + (size_t)n * TT;
    float psum = 0.0f;
    for (int i = tid; i < TT; i += 256) psum += srow[i];
    for (int i = tid; i < TCH; i += 256) ss[i] = srow[t0 + i];
#pragma unroll
    for (int o = 16; o; o >>= 1) psum += __shfl_xor_sync(0xffffffffu, psum, o);
    if ((tid & 31) == 0) red_[tid >> 5] = psum;
    __syncthreads();
    if (tid == 0) {
        float tot = 0.0f;
#pragma unroll
        for (int w = 0; w < 8; w++) tot += red_[w];
        winv_s = 1.0f / fmaxf(tot, 1e-12f);
    }
    __syncthreads();
    int h = blockIdx.x * 256 + tid;
    const float* e = enc + (size_t)n * TT * H2 + (size_t)t0 * H2 + h;
    float a0 = 0.f, a1 = 0.f, a2 = 0.f, a3 = 0.f;
#pragma unroll 1
    for (int t = 0; t + 8 <= TCH; t += 8) {
        a0 += ss[t + 0] * e[(size_t)(t + 0) * H2];
        a1 += ss[t + 1] * e[(size_t)(t + 1) * H2];
        a2 += ss[t + 2] * e[(size_t)(t + 2) * H2];
        a3 += ss[t + 3] * e[(size_t)(t + 3) * H2];
        a0 += ss[t + 4] * e[(size_t)(t + 4) * H2];
        a1 += ss[t + 5] * e[(size_t)(t + 5) * H2];
        a2 += ss[t + 6] * e[(size_t)(t + 6) * H2];
        a3 += ss[t + 7] * e[(size_t)(t + 7) * H2];
    }
    atomicAdd(&dec_in[(size_t)n * H4 + h], (a0 + a1 + a2 + a3) * winv_s);
}

// ---------------------------------------------------------------------------
// Host launch
// ---------------------------------------------------------------------------
static inline GD make_gd(const float* A, int lda, int reluA, const float* W,
                         float* C, int M, int K, int KS) {
    GD d;
    d.A = A; d.W = W; d.C = C;
    d.lda = lda; d.M = M; d.K = K; d.KS = KS; d.reluA = reluA;
    d.nCol = (M + 127) / 128;
    d.start = 0;
    d.nBlocks = d.nCol * ((K + KS - 1) / KS);
    return d;
}

static inline void launch_batch(GD* ds, int n) {
    GemmBatch P;
    int start = 0;
    for (int i = 0; i < n; i++) {
        ds[i].start = start;
        start += ds[i].nBlocks;
        P.d[i] = ds[i];
    }
    for (int i = n; i < 4; i++) P.d[i] = P.d[n - 1];
    P.n = n;
    multi_gemm_kernel<<<start, 256>>>(P);
}

extern "C" void kernel_launch(void* const* d_in, const int* in_sizes, int n_in,
                              void* d_out, int out_size) {
    const float* input_enc   = (const float*)d_in[0];
    const float* attW_enc    = (const float*)d_in[1];
    const float* input_dec   = (const float*)d_in[2];
    const int*   lengths     = (const int*)  d_in[3];
    const float* hidden_att  = (const float*)d_in[4];
    const float* hidden_dec1 = (const float*)d_in[5];
    const float* hidden_dec2 = (const float*)d_in[6];
    const float* W_pre1 = (const float*)d_in[7];
    const float* b_pre1 = (const float*)d_in[8];
    const float* W_pre2 = (const float*)d_in[9];
    const float* b_pre2 = (const float*)d_in[10];
    const float* Wih_att = (const float*)d_in[11];
    const float* Whh_att = (const float*)d_in[12];
    const float* bih_att = (const float*)d_in[13];
    const float* bhh_att = (const float*)d_in[14];
    const float* W_ld  = (const float*)d_in[15];
    const float* b_ld  = (const float*)d_in[16];
    const float* W_attn = (const float*)d_in[17];
    const float* b_attn = (const float*)d_in[18];
    const float* W_sc  = (const float*)d_in[19];
    const float* b_sc  = (const float*)d_in[20];
    const float* Wih_d1 = (const float*)d_in[21];
    const float* Whh_d1 = (const float*)d_in[22];
    const float* bih_d1 = (const float*)d_in[23];
    const float* bhh_d1 = (const float*)d_in[24];
    const float* Wih_d2 = (const float*)d_in[25];
    const float* Whh_d2 = (const float*)d_in[26];
    const float* bih_d2 = (const float*)d_in[27];
    const float* bhh_d2 = (const float*)d_in[28];
    const float* W_out = (const float*)d_in[29];
    const float* b_out = (const float*)d_in[30];

    float* out = (float*)d_out;

    float* sc = nullptr;
    cudaGetSymbolAddress((void**)&sc, g_scratch);

    float* gi_att = sc + OFF_GI_ATT;
    float* gh_att = sc + OFF_GH_ATT;
    float* gi_d1  = sc + OFF_GI_D1;
    float* gh_d1  = sc + OFF_GH_D1;
    float* gi_d2  = sc + OFF_GI_D2;
    float* gh_d2  = sc + OFF_GH_D2;
    float* pre_a  = sc + OFF_PRE_A;
    float* pre    = sc + OFF_PRE;
    float* dp     = sc + OFF_DP;
    float* resid_sc = sc + OFF_RESID_SC;
    float* resid  = sc + OFF_RESID;
    float* resid2 = sc + OFF_RESID2;
    float* dec_in = sc + OFF_DECIN;
    float* score  = sc + OFF_SCORE;

    bool full_out = (out_size >= NB * RR * OO + 3 * NB * H2);
    float* h_att_out = full_out ? out + NB * RR * OO : sc + OFF_HATT;
    float* h_d1_out  = full_out ? h_att_out + NB * H2 : sc + OFF_HD1;
    float* h_d2_out  = full_out ? h_d1_out + NB * H2 : sc + OFF_HD2;

    // 0) zero gates + broadcast biases
    init_kernel<<<(INIT_TOTAL + 255) / 256, 256>>>(out, b_pre1, b_pre2, b_ld, b_sc, b_out);

    // 1) stage A: input-only dependencies (584 CTAs)
    {
        GD ds[4] = {
            make_gd(input_dec,   OO, 0, W_pre1,  pre_a,  H2, OO,   80),
            make_gd(hidden_att,  H2, 0, Whh_att, gh_att, H3, H2,  128),
            make_gd(hidden_dec1, H2, 0, Whh_d1,  gh_d1,  H3, H2,  128),
            make_gd(hidden_dec2, H2, 0, Whh_d2,  gh_d2,  H3, H2,  128),
        };
        launch_batch(ds, 4);
    }
    // 2) pre = relu(pre_a) @ W_pre2^T + b2   (128 CTAs)
    {
        GD ds[1] = { make_gd(pre_a, H2, 1, W_pre2, pre, HH, H2, 32) };
        launch_batch(ds, 1);
    }
    // 3) gi_att = relu(pre) @ Wih_att^T   (384 CTAs)
    {
        GD ds[1] = { make_gd(pre, HH, 1, Wih_att, gi_att, H3, HH, 32) };
        launch_batch(ds, 1);
    }
    // 4) h_att
    gru_combine_kernel<<<(NB * H2 + 255) / 256, 256>>>(
        gi_att, gh_att, bih_att, bhh_att, hidden_att, h_att_out, nullptr, dec_in, 1);
    // 5) dec_proj   (256 CTAs)
    {
        GD ds[1] = { make_gd(h_att_out, H2, 0, W_ld, dp, H2, H2, 32) };
        launch_batch(ds, 1);
    }
    // 6) attention
    attn_score_kernel<<<dim3(TT / 8, NB), 256>>>(attW_enc, dp, W_attn, b_attn,
                                                 lengths, score, dec_in);
    attn_apply_kernel<<<dim3(H2 / 256, NB, TSPLIT), 256>>>(input_enc, score, dec_in);
    // 7) short-cut + decoder GRU 1 input gates   (512 CTAs)
    {
        GD ds[2] = {
            make_gd(dec_in, H4, 0, W_sc,   resid_sc, H2, H4, 128),
            make_gd(dec_in, H4, 0, Wih_d1, gi_d1,    H3, H4, 128),
        };
        launch_batch(ds, 2);
    }
    gru_combine_kernel<<<(NB * H2 + 255) / 256, 256>>>(
        gi_d1, gh_d1, bih_d1, bhh_d1, hidden_dec1, h_d1_out, resid_sc, resid, 2);
    // 8) decoder GRU 2   (384 CTAs)
    {
        GD ds[1] = { make_gd(resid, H2, 0, Wih_d2, gi_d2, H3, H2, 64) };
        launch_batch(ds, 1);
    }
    gru_combine_kernel<<<(NB * H2 + 255) / 256, 256>>>(
        gi_d2, gh_d2, bih_d2, bhh_d2, hidden_dec2, h_d2_out, resid, resid2, 2);
    // 9) output projection   (128 CTAs)
    {
        GD ds[1] = { make_gd(resid2, H2, 0, W_out, out, RR * OO, H2, 16) };
        launch_batch(ds, 1);
    }
}

// round 4
// speedup vs baseline: 2.7580x; 1.5406x over previous
#include <cuda_runtime.h>
#include <math.h>

// ---------------------------------------------------------------------------
// Problem constants
// ---------------------------------------------------------------------------
#define NB   64
#define TT   800
#define HH   512
#define H2   1024
#define H3   3072   // 3*H2
#define H4   2048   // 4*H
#define OO   80
#define RR   2

typedef unsigned long long ull;

// ---------------------------------------------------------------------------
// Scratch
// ---------------------------------------------------------------------------
#define GSZ       (NB * H3)
#define OFF_GI_ATT   0
#define OFF_GH_ATT   (1 * GSZ)
#define OFF_GI_D1    (2 * GSZ)
#define OFF_GH_D1    (3 * GSZ)
#define OFF_GI_D2    (4 * GSZ)
#define OFF_GH_D2    (5 * GSZ)
#define OFF_PRE_A    (6 * GSZ)
#define OFF_PRE      (OFF_PRE_A   + NB * H2)
#define OFF_DP       (OFF_PRE     + NB * HH)
#define OFF_RESID_SC (OFF_DP      + NB * H2)
#define OFF_RESID    (OFF_RESID_SC+ NB * H2)
#define OFF_RESID2   (OFF_RESID   + NB * H2)
#define OFF_DECIN    (OFF_RESID2  + NB * H2)
#define OFF_SSUM     (OFF_DECIN   + NB * H4)
#define OFF_HATT     (OFF_SSUM    + 64)
#define OFF_HD1      (OFF_HATT    + NB * H2)
#define OFF_HD2      (OFF_HD1     + NB * H2)
#define SCRATCH_TOTAL (OFF_HD2    + NB * H2)

__device__ float g_scratch[SCRATCH_TOTAL];

// ---------------------------------------------------------------------------
// Math helpers
// ---------------------------------------------------------------------------
__device__ __forceinline__ float fast_tanh(float x) {
    float e = __expf(2.0f * x);
    return 1.0f - 2.0f / (e + 1.0f);
}
__device__ __forceinline__ float approx_tanh(float x) {
    float y;
    asm("tanh.approx.f32 %0, %1;" : "=f"(y) : "f"(x));
    return y;
}
__device__ __forceinline__ float fast_sigmoid(float x) {
    return 1.0f / (1.0f + __expf(-x));
}

__device__ __forceinline__ ull pk2(float x, float y) {
    ull r;
    asm("mov.b64 %0, {%1, %2};" : "=l"(r) : "f"(x), "f"(y));
    return r;
}
__device__ __forceinline__ void upk2(ull v, float& x, float& y) {
    asm("mov.b64 {%0, %1}, %2;" : "=f"(x), "=f"(y) : "l"(v));
}
__device__ __forceinline__ void ffma2(ull& d, ull a, ull b) {
    asm("fma.rn.f32x2 %0, %1, %2, %0;" : "+l"(d) : "l"(a), "l"(b));
}
__device__ __forceinline__ void red4(float* p, float x, float y, float z, float w) {
    asm volatile("red.global.add.v4.f32 [%0], {%1,%2,%3,%4};"
                 :: "l"(p), "f"(x), "f"(y), "f"(z), "f"(w) : "memory");
}

// ---------------------------------------------------------------------------
// Init: zero gate buffers + dec_in attn half + ssum, broadcast biases
// ---------------------------------------------------------------------------
#define INIT_TOTAL (6 * GSZ + NB * H2 + NB * HH + NB * H2 + NB * H2 + NB * RR * OO + NB * H2 + 64)

__global__ void init_kernel(float* __restrict__ out,
                            const float* __restrict__ b_pre1,
                            const float* __restrict__ b_pre2,
                            const float* __restrict__ b_ld,
                            const float* __restrict__ b_sc,
                            const float* __restrict__ b_out) {
    int idx = blockIdx.x * 256 + threadIdx.x;
    if (idx < 6 * GSZ) { g_scratch[idx] = 0.0f; return; }
    idx -= 6 * GSZ;
    if (idx < NB * H2) { g_scratch[OFF_PRE_A + idx] = b_pre1[idx & (H2 - 1)]; return; }
    idx -= NB * H2;
    if (idx < NB * HH) { g_scratch[OFF_PRE + idx] = b_pre2[idx & (HH - 1)]; return; }
    idx -= NB * HH;
    if (idx < NB * H2) { g_scratch[OFF_DP + idx] = b_ld[idx & (H2 - 1)]; return; }
    idx -= NB * H2;
    if (idx < NB * H2) { g_scratch[OFF_RESID_SC + idx] = b_sc[idx & (H2 - 1)]; return; }
    idx -= NB * H2;
    if (idx < NB * RR * OO) { out[idx] = b_out[idx % (RR * OO)]; return; }
    idx -= NB * RR * OO;
    if (idx < NB * H2) {
        int n = idx >> 10, j = idx & (H2 - 1);
        g_scratch[OFF_DECIN + (size_t)n * H4 + j] = 0.0f;   // dec_in[:, 0:1024]
        return;
    }
    idx -= NB * H2;
    if (idx < 64) { g_scratch[OFF_SSUM + idx] = 0.0f; return; }
}

// ---------------------------------------------------------------------------
// Batched skinny GEMM: C[64, M] += A'[64, K] * W[M, K]^T   (A' = transformed A)
// 64x128 tile, 256 threads, 8 rows x 4 cols per thread, f32x2 with row-pair
// accumulators. Whole K-slice staged to smem once (<=48KB), single sync.
// mode: 0 = identity, 1 = relu(A), 2 = divide cols k<1024 by ssum[row]
// Requires K % KS == 0, KS % 16 == 0, KS <= 64.
// ---------------------------------------------------------------------------
#define KSMAX 64

struct GD {
    const float* A;
    const float* W;
    float* C;
    const float* ssum;
    int lda, M, K, KS, mode, nCol, start, nBlocks;
};
struct GemmBatch { GD d[4]; int n; };

__global__ void __launch_bounds__(256, 3) multi_gemm_kernel(GemmBatch P) {
    __shared__ float As[KSMAX * 64];    // As[k*64 + row]
    __shared__ float Ws[KSMAX * 128];   // Ws[k*128 + col]

    int b = blockIdx.x;
    GD d = P.d[0];
#pragma unroll
    for (int i = 1; i < 4; i++) {
        if (i < P.n && b >= P.d[i].start) d = P.d[i];
    }
    int lb = b - d.start;
    int colBlock = lb % d.nCol;
    int kBlock = lb / d.nCol;
    int colBase = colBlock * 128;
    int k0 = kBlock * d.KS;

    int tid = threadIdx.x;
    int ty = tid >> 5;
    int tx = tid & 31;

    // ---- stage whole slice ----
    int arow = tid & 63;
    int akk  = (tid >> 6) << 2;          // 0,4,8,12
    int wcol = tid & 127;
    int wkk  = (tid >> 7) << 2;          // 0,4
    int gc = colBase + wcol;
    bool wvalid = (gc < d.M);

    float wv = 1.0f;
    if (d.mode == 2) wv = 1.0f / fmaxf(d.ssum[arow], 1e-12f);

    const float* aptr = d.A + (size_t)arow * d.lda + k0 + akk;
    const float* wptr = d.W + (size_t)gc * d.K + k0 + wkk;

    int nslab = d.KS >> 4;
#pragma unroll 4
    for (int s = 0; s < nslab; s++) {
        float4 v = *(const float4*)(aptr + s * 16);
        if (d.mode == 1) {
            v.x = fmaxf(v.x, 0.f); v.y = fmaxf(v.y, 0.f);
            v.z = fmaxf(v.z, 0.f); v.w = fmaxf(v.w, 0.f);
        } else if (d.mode == 2 && (k0 + s * 16 + akk) < H2) {
            v.x *= wv; v.y *= wv; v.z *= wv; v.w *= wv;
        }
        int kb = s * 16 + akk;
        As[(kb + 0) * 64 + arow] = v.x; As[(kb + 1) * 64 + arow] = v.y;
        As[(kb + 2) * 64 + arow] = v.z; As[(kb + 3) * 64 + arow] = v.w;

        float4 u0 = make_float4(0.f, 0.f, 0.f, 0.f);
        float4 u1 = make_float4(0.f, 0.f, 0.f, 0.f);
        if (wvalid) {
            u0 = *(const float4*)(wptr + s * 16);
            u1 = *(const float4*)(wptr + s * 16 + 8);
        }
        int kw = s * 16 + wkk;
        Ws[(kw + 0) * 128 + wcol] = u0.x; Ws[(kw + 1) * 128 + wcol] = u0.y;
        Ws[(kw + 2) * 128 + wcol] = u0.z; Ws[(kw + 3) * 128 + wcol] = u0.w;
        Ws[(kw + 8) * 128 + wcol] = u1.x; Ws[(kw + 9) * 128 + wcol] = u1.y;
        Ws[(kw +10) * 128 + wcol] = u1.z; Ws[(kw +11) * 128 + wcol] = u1.w;
    }
    __syncthreads();

    // ---- compute ----
    ull acc[4][4];
#pragma unroll
    for (int p = 0; p < 4; p++)
#pragma unroll
        for (int j = 0; j < 4; j++) acc[p][j] = pk2(0.0f, 0.0f);

#pragma unroll 4
    for (int kk = 0; kk < d.KS; kk++) {
        const float* abase = &As[kk * 64 + ty * 8];
        ulonglong2 Ap0 = *(const ulonglong2*)(abase);       // rows 0-1, 2-3
        ulonglong2 Ap1 = *(const ulonglong2*)(abase + 4);   // rows 4-5, 6-7
        float4 bv = *(const float4*)&Ws[kk * 128 + tx * 4];
        ull b0 = pk2(bv.x, bv.x);
        ull b1 = pk2(bv.y, bv.y);
        ull b2 = pk2(bv.z, bv.z);
        ull b3 = pk2(bv.w, bv.w);
        ffma2(acc[0][0], Ap0.x, b0); ffma2(acc[0][1], Ap0.x, b1);
        ffma2(acc[0][2], Ap0.x, b2); ffma2(acc[0][3], Ap0.x, b3);
        ffma2(acc[1][0], Ap0.y, b0); ffma2(acc[1][1], Ap0.y, b1);
        ffma2(acc[1][2], Ap0.y, b2); ffma2(acc[1][3], Ap0.y, b3);
        ffma2(acc[2][0], Ap1.x, b0); ffma2(acc[2][1], Ap1.x, b1);
        ffma2(acc[2][2], Ap1.x, b2); ffma2(acc[2][3], Ap1.x, b3);
        ffma2(acc[3][0], Ap1.y, b0); ffma2(acc[3][1], Ap1.y, b1);
        ffma2(acc[3][2], Ap1.y, b2); ffma2(acc[3][3], Ap1.y, b3);
    }

    // ---- epilogue ----
    int col = colBase + tx * 4;
    if (col < d.M) {
#pragma unroll
        for (int p = 0; p < 4; p++) {
            int r0 = ty * 8 + 2 * p;
            float lo0, hi0, lo1, hi1, lo2, hi2, lo3, hi3;
            upk2(acc[p][0], lo0, hi0);
            upk2(acc[p][1], lo1, hi1);
            upk2(acc[p][2], lo2, hi2);
            upk2(acc[p][3], lo3, hi3);
            red4(&d.C[(size_t)r0 * d.M + col], lo0, lo1, lo2, lo3);
            red4(&d.C[(size_t)(r0 + 1) * d.M + col], hi0, hi1, hi2, hi3);
        }
    }
}

// ---------------------------------------------------------------------------
// GRU combine
// ---------------------------------------------------------------------------
__global__ void gru_combine_kernel(const float* __restrict__ gi,
                                   const float* __restrict__ gh,
                                   const float* __restrict__ bih,
                                   const float* __restrict__ bhh,
                                   const float* __restrict__ hprev,
                                   float* __restrict__ hout,
                                   const float* __restrict__ extra_in,
                                   float* __restrict__ extra_out,
                                   int mode) {
    int idx = blockIdx.x * 256 + threadIdx.x;
    if (idx >= NB * H2) return;
    int n = idx >> 10;
    int j = idx & (H2 - 1);
    const float* gin = gi + (size_t)n * H3;
    const float* ghn = gh + (size_t)n * H3;
    float ir = gin[j]          + bih[j];
    float iz = gin[j + H2]     + bih[j + H2];
    float in_ = gin[j + 2*H2]  + bih[j + 2*H2];
    float hr = ghn[j]          + bhh[j];
    float hz = ghn[j + H2]     + bhh[j + H2];
    float hn = ghn[j + 2*H2]   + bhh[j + 2*H2];
    float r = fast_sigmoid(ir + hr);
    float z = fast_sigmoid(iz + hz);
    float nn = fast_tanh(in_ + r * hn);
    float h = (1.0f - z) * nn + z * hprev[idx];
    hout[idx] = h;
    if (mode == 1) {
        extra_out[(size_t)n * H4 + H2 + j] = h;
    } else if (mode == 2) {
        extra_out[idx] = extra_in[idx] + h;
    }
}

// ---------------------------------------------------------------------------
// Fused attention: per (n, 16-t chunk) block:
//   scores (tanh + dot + exp), then unnormalized apply into dec_in[:, :1024]
//   (red.v4) and score-sum into ssum[n]. Normalization folded into the
//   consumer GEMM A-load (mode 2).
// ---------------------------------------------------------------------------
#define CH 16

__global__ void __launch_bounds__(256) attn_fused_kernel(
    const float* __restrict__ attW, const float* __restrict__ enc,
    const float* __restrict__ dp, const float* __restrict__ Wattn,
    const float* __restrict__ battn, const int* __restrict__ lengths,
    float* __restrict__ dec_in, float* __restrict__ ssum) {
    __shared__ float dps[H2];
    __shared__ float was[H2];
    __shared__ float ss[CH];
    int n = blockIdx.y;
    int t0 = blockIdx.x * CH;
    int len = lengths[n];
    if (t0 >= len) return;
    int kmax = min(CH, len - t0);
    int tid = threadIdx.x;

    for (int i = tid; i < H2; i += 256) {
        dps[i] = dp[(size_t)n * H2 + i];
        was[i] = Wattn[i];
    }
    if (tid < CH) ss[tid] = 0.0f;
    __syncthreads();

    int warp = tid >> 5, lane = tid & 31;
    float bb = battn[0];
#pragma unroll
    for (int rep = 0; rep < 2; rep++) {
        int lt = warp + rep * 8;
        if (lt < kmax) {
            const float4* row = (const float4*)(attW + ((size_t)n * TT + t0 + lt) * H2);
            const float4* d4p = (const float4*)dps;
            const float4* w4p = (const float4*)was;
            float s = 0.0f;
#pragma unroll
            for (int it = 0; it < 8; it++) {
                int i = it * 32 + lane;
                float4 v = row[i];
                float4 dd = d4p[i];
                float4 ww = w4p[i];
                s += approx_tanh(v.x + dd.x) * ww.x
                   + approx_tanh(v.y + dd.y) * ww.y
                   + approx_tanh(v.z + dd.z) * ww.z
                   + approx_tanh(v.w + dd.w) * ww.w;
            }
#pragma unroll
            for (int o = 16; o; o >>= 1) s += __shfl_xor_sync(0xffffffffu, s, o);
            if (lane == 0) ss[lt] = __expf(s + bb);
        }
    }
    __syncthreads();

    if (warp == 0) {
        float v = (lane < CH) ? ss[lane] : 0.0f;
#pragma unroll
        for (int o = 16; o; o >>= 1) v += __shfl_xor_sync(0xffffffffu, v, o);
        if (lane == 0) atomicAdd(&ssum[n], v);
    }

    int h = tid * 4;
    const float* ebase = enc + (size_t)n * TT * H2 + (size_t)t0 * H2 + h;
    float ax = 0.f, ay = 0.f, az = 0.f, aw = 0.f;
#pragma unroll 4
    for (int t = 0; t < kmax; t++) {
        float w = ss[t];
        float4 e = *(const float4*)(ebase + (size_t)t * H2);
        ax += w * e.x; ay += w * e.y; az += w * e.z; aw += w * e.w;
    }
    red4(&dec_in[(size_t)n * H4 + h], ax, ay, az, aw);
}

// ---------------------------------------------------------------------------
// Host launch
// ---------------------------------------------------------------------------
static inline GD make_gd(const float* A, int lda, int mode, const float* W,
                         float* C, int M, int K, int KS, const float* ssum) {
    GD d;
    d.A = A; d.W = W; d.C = C; d.ssum = ssum;
    d.lda = lda; d.M = M; d.K = K; d.KS = KS; d.mode = mode;
    d.nCol = (M + 127) / 128;
    d.start = 0;
    d.nBlocks = d.nCol * (K / KS);
    return d;
}

static inline void launch_batch(GD* ds, int n) {
    GemmBatch P;
    int start = 0;
    for (int i = 0; i < n; i++) {
        ds[i].start = start;
        start += ds[i].nBlocks;
        P.d[i] = ds[i];
    }
    for (int i = n; i < 4; i++) P.d[i] = P.d[n - 1];
    P.n = n;
    multi_gemm_kernel<<<start, 256>>>(P);
}

extern "C" void kernel_launch(void* const* d_in, const int* in_sizes, int n_in,
                              void* d_out, int out_size) {
    const float* input_enc   = (const float*)d_in[0];
    const float* attW_enc    = (const float*)d_in[1];
    const float* input_dec   = (const float*)d_in[2];
    const int*   lengths     = (const int*)  d_in[3];
    const float* hidden_att  = (const float*)d_in[4];
    const float* hidden_dec1 = (const float*)d_in[5];
    const float* hidden_dec2 = (const float*)d_in[6];
    const float* W_pre1 = (const float*)d_in[7];
    const float* b_pre1 = (const float*)d_in[8];
    const float* W_pre2 = (const float*)d_in[9];
    const float* b_pre2 = (const float*)d_in[10];
    const float* Wih_att = (const float*)d_in[11];
    const float* Whh_att = (const float*)d_in[12];
    const float* bih_att = (const float*)d_in[13];
    const float* bhh_att = (const float*)d_in[14];
    const float* W_ld  = (const float*)d_in[15];
    const float* b_ld  = (const float*)d_in[16];
    const float* W_attn = (const float*)d_in[17];
    const float* b_attn = (const float*)d_in[18];
    const float* W_sc  = (const float*)d_in[19];
    const float* b_sc  = (const float*)d_in[20];
    const float* Wih_d1 = (const float*)d_in[21];
    const float* Whh_d1 = (const float*)d_in[22];
    const float* bih_d1 = (const float*)d_in[23];
    const float* bhh_d1 = (const float*)d_in[24];
    const float* Wih_d2 = (const float*)d_in[25];
    const float* Whh_d2 = (const float*)d_in[26];
    const float* bih_d2 = (const float*)d_in[27];
    const float* bhh_d2 = (const float*)d_in[28];
    const float* W_out = (const float*)d_in[29];
    const float* b_out = (const float*)d_in[30];

    float* out = (float*)d_out;

    float* sc = nullptr;
    cudaGetSymbolAddress((void**)&sc, g_scratch);

    float* gi_att = sc + OFF_GI_ATT;
    float* gh_att = sc + OFF_GH_ATT;
    float* gi_d1  = sc + OFF_GI_D1;
    float* gh_d1  = sc + OFF_GH_D1;
    float* gi_d2  = sc + OFF_GI_D2;
    float* gh_d2  = sc + OFF_GH_D2;
    float* pre_a  = sc + OFF_PRE_A;
    float* pre    = sc + OFF_PRE;
    float* dp     = sc + OFF_DP;
    float* resid_sc = sc + OFF_RESID_SC;
    float* resid  = sc + OFF_RESID;
    float* resid2 = sc + OFF_RESID2;
    float* dec_in = sc + OFF_DECIN;
    float* ssum   = sc + OFF_SSUM;

    bool full_out = (out_size >= NB * RR * OO + 3 * NB * H2);
    float* h_att_out = full_out ? out + NB * RR * OO : sc + OFF_HATT;
    float* h_d1_out  = full_out ? h_att_out + NB * H2 : sc + OFF_HD1;
    float* h_d2_out  = full_out ? h_d1_out + NB * H2 : sc + OFF_HD2;

    // 0) zero gates/dec_in/ssum + broadcast biases
    init_kernel<<<(INIT_TOTAL + 255) / 256, 256>>>(out, b_pre1, b_pre2, b_ld, b_sc, b_out);

    // 1) stage A: input-only dependencies (40 + 3*768 = 2344 CTAs)
    {
        GD ds[4] = {
            make_gd(input_dec,   OO, 0, W_pre1,  pre_a,  H2, OO,   16, nullptr),
            make_gd(hidden_att,  H2, 0, Whh_att, gh_att, H3, H2,   32, nullptr),
            make_gd(hidden_dec1, H2, 0, Whh_d1,  gh_d1,  H3, H2,   32, nullptr),
            make_gd(hidden_dec2, H2, 0, Whh_d2,  gh_d2,  H3, H2,   32, nullptr),
        };
        launch_batch(ds, 4);
    }
    // 2) pre = relu(pre_a) @ W_pre2^T + b2   (256 CTAs)
    {
        GD ds[1] = { make_gd(pre_a, H2, 1, W_pre2, pre, HH, H2, 16, nullptr) };
        launch_batch(ds, 1);
    }
    // 3) gi_att = relu(pre) @ Wih_att^T   (384 CTAs)
    {
        GD ds[1] = { make_gd(pre, HH, 1, Wih_att, gi_att, H3, HH, 32, nullptr) };
        launch_batch(ds, 1);
    }
    // 4) h_att
    gru_combine_kernel<<<(NB * H2 + 255) / 256, 256>>>(
        gi_att, gh_att, bih_att, bhh_att, hidden_att, h_att_out, nullptr, dec_in, 1);
    // 5) dec_proj   (512 CTAs)
    {
        GD ds[1] = { make_gd(h_att_out, H2, 0, W_ld, dp, H2, H2, 16, nullptr) };
        launch_batch(ds, 1);
    }
    // 6) fused attention (3200 CTAs)
    attn_fused_kernel<<<dim3(TT / CH, NB), 256>>>(attW_enc, input_enc, dp,
                                                  W_attn, b_attn, lengths,
                                                  dec_in, ssum);
    // 7) short-cut + decoder GRU 1 input gates (mode 2 normalizes attn half; 1024 CTAs)
    {
        GD ds[2] = {
            make_gd(dec_in, H4, 2, W_sc,   resid_sc, H2, H4, 64, ssum),
            make_gd(dec_in, H4, 2, Wih_d1, gi_d1,    H3, H4, 64, ssum),
        };
        launch_batch(ds, 2);
    }
    gru_combine_kernel<<<(NB * H2 + 255) / 256, 256>>>(
        gi_d1, gh_d1, bih_d1, bhh_d1, hidden_dec1, h_d1_out, resid_sc, resid, 2);
    // 8) decoder GRU 2   (768 CTAs)
    {
        GD ds[1] = { make_gd(resid, H2, 0, Wih_d2, gi_d2, H3, H2, 32, nullptr) };
        launch_batch(ds, 1);
    }
    gru_combine_kernel<<<(NB * H2 + 255) / 256, 256>>>(
        gi_d2, gh_d2, bih_d2, bhh_d2, hidden_dec2, h_d2_out, resid, resid2, 2);
    // 9) output projection   (128 CTAs)
    {
        GD ds[1] = { make_gd(resid2, H2, 0, W_out, out, RR * OO, H2, 16, nullptr) };
        launch_batch(ds, 1);
    }
}

// round 6
// speedup vs baseline: 2.8711x; 1.0410x over previous
#include <cuda_runtime.h>
#include <math.h>

// ---------------------------------------------------------------------------
// Problem constants
// ---------------------------------------------------------------------------
#define NB   64
#define TT   800
#define HH   512
#define H2   1024
#define H3   3072   // 3*H2
#define H4   2048   // 4*H
#define OO   80
#define RR   2

typedef unsigned long long ull;

// ---------------------------------------------------------------------------
// Scratch
// ---------------------------------------------------------------------------
#define GSZ       (NB * H3)
#define OFF_GI_ATT   0
#define OFF_GH_ATT   (1 * GSZ)
#define OFF_GI_D1    (2 * GSZ)
#define OFF_GH_D1    (3 * GSZ)
#define OFF_GI_D2    (4 * GSZ)
#define OFF_GH_D2    (5 * GSZ)
#define OFF_PRE_A    (6 * GSZ)
#define OFF_PRE      (OFF_PRE_A   + NB * H2)
#define OFF_DP       (OFF_PRE     + NB * HH)
#define OFF_RESID_SC (OFF_DP      + NB * H2)
#define OFF_RESID    (OFF_RESID_SC+ NB * H2)
#define OFF_RESID2   (OFF_RESID   + NB * H2)
#define OFF_DECIN    (OFF_RESID2  + NB * H2)
#define OFF_SSUM     (OFF_DECIN   + NB * H4)
#define OFF_FLAGS    (OFF_SSUM    + 64)               // 3 ints (stored as floats slot)
#define OFF_HATT     (OFF_FLAGS   + 16)
#define OFF_HD1      (OFF_HATT    + NB * H2)
#define OFF_HD2      (OFF_HD1     + NB * H2)
#define SCRATCH_TOTAL (OFF_HD2    + NB * H2)

__device__ float g_scratch[SCRATCH_TOTAL];

// ---------------------------------------------------------------------------
// Math helpers
// ---------------------------------------------------------------------------
__device__ __forceinline__ float fast_tanh(float x) {
    float e = __expf(2.0f * x);
    return 1.0f - 2.0f / (e + 1.0f);
}
__device__ __forceinline__ float approx_tanh(float x) {
    float y;
    asm("tanh.approx.f32 %0, %1;" : "=f"(y) : "f"(x));
    return y;
}
__device__ __forceinline__ float fast_sigmoid(float x) {
    return 1.0f / (1.0f + __expf(-x));
}

__device__ __forceinline__ ull pk2(float x, float y) {
    ull r;
    asm("mov.b64 %0, {%1, %2};" : "=l"(r) : "f"(x), "f"(y));
    return r;
}
__device__ __forceinline__ void upk2(ull v, float& x, float& y) {
    asm("mov.b64 {%0, %1}, %2;" : "=f"(x), "=f"(y) : "l"(v));
}
__device__ __forceinline__ void ffma2(ull& d, ull a, ull b) {
    asm("fma.rn.f32x2 %0, %1, %2, %0;" : "+l"(d) : "l"(a), "l"(b));
}
__device__ __forceinline__ void red4(float* p, float x, float y, float z, float w) {
    asm volatile("red.global.add.v4.f32 [%0], {%1,%2,%3,%4};"
                 :: "l"(p), "f"(x), "f"(y), "f"(z), "f"(w) : "memory");
}

// ---------------------------------------------------------------------------
// Precheck: flags[b] = any nonzero in hidden matrix b  (single writer, no race)
// ---------------------------------------------------------------------------
__global__ void precheck_kernel(const float* __restrict__ h0,
                                const float* __restrict__ h1,
                                const float* __restrict__ h2) {
    const float* p = (blockIdx.x == 0) ? h0 : ((blockIdx.x == 1) ? h1 : h2);
    int any = 0;
    for (int i = threadIdx.x; i < NB * H2; i += 1024)
        any |= (p[i] != 0.0f);
    int r = __syncthreads_or(any);
    if (threadIdx.x == 0)
        ((int*)(g_scratch + OFF_FLAGS))[blockIdx.x] = r;
}

// ---------------------------------------------------------------------------
// Init: zero gate buffers + dec_in attn half + ssum, broadcast biases
// ---------------------------------------------------------------------------
#define INIT_TOTAL (6 * GSZ + NB * H2 + NB * HH + NB * H2 + NB * H2 + NB * RR * OO + NB * H2 + 64)

__global__ void init_kernel(float* __restrict__ out,
                            const float* __restrict__ b_pre1,
                            const float* __restrict__ b_pre2,
                            const float* __restrict__ b_ld,
                            const float* __restrict__ b_sc,
                            const float* __restrict__ b_out) {
    int idx = blockIdx.x * 256 + threadIdx.x;
    if (idx < 6 * GSZ) { g_scratch[idx] = 0.0f; return; }
    idx -= 6 * GSZ;
    if (idx < NB * H2) { g_scratch[OFF_PRE_A + idx] = b_pre1[idx & (H2 - 1)]; return; }
    idx -= NB * H2;
    if (idx < NB * HH) { g_scratch[OFF_PRE + idx] = b_pre2[idx & (HH - 1)]; return; }
    idx -= NB * HH;
    if (idx < NB * H2) { g_scratch[OFF_DP + idx] = b_ld[idx & (H2 - 1)]; return; }
    idx -= NB * H2;
    if (idx < NB * H2) { g_scratch[OFF_RESID_SC + idx] = b_sc[idx & (H2 - 1)]; return; }
    idx -= NB * H2;
    if (idx < NB * RR * OO) { out[idx] = b_out[idx % (RR * OO)]; return; }
    idx -= NB * RR * OO;
    if (idx < NB * H2) {
        int n = idx >> 10, j = idx & (H2 - 1);
        g_scratch[OFF_DECIN + (size_t)n * H4 + j] = 0.0f;
        return;
    }
    idx -= NB * H2;
    if (idx < 64) { g_scratch[OFF_SSUM + idx] = 0.0f; return; }
}

// ---------------------------------------------------------------------------
// Batched skinny GEMM: C[64, M] += A'[64, K] * W[M, K]^T
// 64x64 tile, 128 threads, 8 rows x 4 cols per thread, f32x2 row-pair accums.
// Two-level K: register accumulators persist over KS/inner smem refills.
// mode: 0 = identity, 1 = relu(A), 2 = divide cols k<1024 by ssum[row]
// Requires K % KS == 0, KS % inner == 0, inner in {16,32}.
// skip: optional device flag; if *skip==0 the A operand is all-zero -> return.
// ---------------------------------------------------------------------------
#define GIN_MAX 32

struct GD {
    const float* A;
    const float* W;
    float* C;
    const float* ssum;
    const int* skip;
    int lda, M, K, KS, inner, mode, nCol, start, nBlocks;
};
struct GemmBatch { GD d[4]; int n; };

__global__ void __launch_bounds__(128, 6) multi_gemm_kernel(GemmBatch P) {
    __shared__ float As[GIN_MAX * 64];
    __shared__ float Ws[GIN_MAX * 64];

    int b = blockIdx.x;
    GD d = P.d[0];
#pragma unroll
    for (int i = 1; i < 4; i++) {
        if (i < P.n && b >= P.d[i].start) d = P.d[i];
    }
    if (d.skip && *d.skip == 0) return;   // A provably all-zero -> C += 0

    int lb = b - d.start;
    int colBlock = lb % d.nCol;
    int kBlock = lb / d.nCol;
    int colBase = colBlock * 64;
    int k0 = kBlock * d.KS;

    int tid = threadIdx.x;
    int ty = tid >> 4;          // 0..7 -> rows ty*8..ty*8+7
    int tx = tid & 15;          // 0..15 -> cols tx*4..tx*4+3

    int arow = tid & 63;
    int half = tid >> 6;        // 0/1
    int wcol = tid & 63;
    int gc = colBase + wcol;
    bool wvalid = (gc < d.M);

    float wv = 1.0f;
    if (d.mode == 2) wv = 1.0f / fmaxf(d.ssum[arow], 1e-12f);

    const float* aptr = d.A + (size_t)arow * d.lda;
    const float* wptr = d.W + (size_t)(wvalid ? gc : 0) * d.K;

    ull acc[4][4];
#pragma unroll
    for (int p = 0; p < 4; p++)
#pragma unroll
        for (int j = 0; j < 4; j++) acc[p][j] = pk2(0.0f, 0.0f);

    int nref = d.KS / d.inner;
    int hk = d.inner >> 1;      // k-columns per half
    int nf4 = hk >> 2;          // float4 loads per thread (2 or 4)

    for (int rf = 0; rf < nref; rf++) {
        int kb = k0 + rf * d.inner;
#pragma unroll 4
        for (int q = 0; q < nf4; q++) {
            int kl = half * hk + q * 4;
            float4 v = *(const float4*)(aptr + kb + kl);
            if (d.mode == 1) {
                v.x = fmaxf(v.x, 0.f); v.y = fmaxf(v.y, 0.f);
                v.z = fmaxf(v.z, 0.f); v.w = fmaxf(v.w, 0.f);
            } else if (d.mode == 2 && (kb + kl) < H2) {
                v.x *= wv; v.y *= wv; v.z *= wv; v.w *= wv;
            }
            As[(kl + 0) * 64 + arow] = v.x; As[(kl + 1) * 64 + arow] = v.y;
            As[(kl + 2) * 64 + arow] = v.z; As[(kl + 3) * 64 + arow] = v.w;

            float4 u = make_float4(0.f, 0.f, 0.f, 0.f);
            if (wvalid) u = *(const float4*)(wptr + kb + kl);
            Ws[(kl + 0) * 64 + wcol] = u.x; Ws[(kl + 1) * 64 + wcol] = u.y;
            Ws[(kl + 2) * 64 + wcol] = u.z; Ws[(kl + 3) * 64 + wcol] = u.w;
        }
        __syncthreads();
#pragma unroll 4
        for (int kk = 0; kk < d.inner; kk++) {
            const float* ab = &As[kk * 64 + ty * 8];
            ulonglong2 Ap0 = *(const ulonglong2*)(ab);
            ulonglong2 Ap1 = *(const ulonglong2*)(ab + 4);
            float4 bv = *(const float4*)&Ws[kk * 64 + tx * 4];
            ull b0 = pk2(bv.x, bv.x);
            ull b1 = pk2(bv.y, bv.y);
            ull b2 = pk2(bv.z, bv.z);
            ull b3 = pk2(bv.w, bv.w);
            ffma2(acc[0][0], Ap0.x, b0); ffma2(acc[0][1], Ap0.x, b1);
            ffma2(acc[0][2], Ap0.x, b2); ffma2(acc[0][3], Ap0.x, b3);
            ffma2(acc[1][0], Ap0.y, b0); ffma2(acc[1][1], Ap0.y, b1);
            ffma2(acc[1][2], Ap0.y, b2); ffma2(acc[1][3], Ap0.y, b3);
            ffma2(acc[2][0], Ap1.x, b0); ffma2(acc[2][1], Ap1.x, b1);
            ffma2(acc[2][2], Ap1.x, b2); ffma2(acc[2][3], Ap1.x, b3);
            ffma2(acc[3][0], Ap1.y, b0); ffma2(acc[3][1], Ap1.y, b1);
            ffma2(acc[3][2], Ap1.y, b2); ffma2(acc[3][3], Ap1.y, b3);
        }
        __syncthreads();
    }

    int col = colBase + tx * 4;
    if (col < d.M) {
#pragma unroll
        for (int p = 0; p < 4; p++) {
            int r0 = ty * 8 + 2 * p;
            float lo0, hi0, lo1, hi1, lo2, hi2, lo3, hi3;
            upk2(acc[p][0], lo0, hi0);
            upk2(acc[p][1], lo1, hi1);
            upk2(acc[p][2], lo2, hi2);
            upk2(acc[p][3], lo3, hi3);
            red4(&d.C[(size_t)r0 * d.M + col], lo0, lo1, lo2, lo3);
            red4(&d.C[(size_t)(r0 + 1) * d.M + col], hi0, hi1, hi2, hi3);
        }
    }
}

// ---------------------------------------------------------------------------
// GRU combine
// ---------------------------------------------------------------------------
__global__ void gru_combine_kernel(const float* __restrict__ gi,
                                   const float* __restrict__ gh,
                                   const float* __restrict__ bih,
                                   const float* __restrict__ bhh,
                                   const float* __restrict__ hprev,
                                   float* __restrict__ hout,
                                   const float* __restrict__ extra_in,
                                   float* __restrict__ extra_out,
                                   int mode) {
    int idx = blockIdx.x * 256 + threadIdx.x;
    if (idx >= NB * H2) return;
    int n = idx >> 10;
    int j = idx & (H2 - 1);
    const float* gin = gi + (size_t)n * H3;
    const float* ghn = gh + (size_t)n * H3;
    float ir = gin[j]          + bih[j];
    float iz = gin[j + H2]     + bih[j + H2];
    float in_ = gin[j + 2*H2]  + bih[j + 2*H2];
    float hr = ghn[j]          + bhh[j];
    float hz = ghn[j + H2]     + bhh[j + H2];
    float hn = ghn[j + 2*H2]   + bhh[j + 2*H2];
    float r = fast_sigmoid(ir + hr);
    float z = fast_sigmoid(iz + hz);
    float nn = fast_tanh(in_ + r * hn);
    float h = (1.0f - z) * nn + z * hprev[idx];
    hout[idx] = h;
    if (mode == 1) {
        extra_out[(size_t)n * H4 + H2 + j] = h;
    } else if (mode == 2) {
        extra_out[idx] = extra_in[idx] + h;
    }
}

// ---------------------------------------------------------------------------
// Fused attention: per (n, 32-t chunk) block:
//   scores (tanh + dot + exp), unnormalized apply into dec_in[:, :1024] via
//   red.v4, score-sum into ssum[n]. Normalization folded into consumer GEMM.
// ---------------------------------------------------------------------------
#define CH 32

__global__ void __launch_bounds__(256) attn_fused_kernel(
    const float* __restrict__ attW, const float* __restrict__ enc,
    const float* __restrict__ dp, const float* __restrict__ Wattn,
    const float* __restrict__ battn, const int* __restrict__ lengths,
    float* __restrict__ dec_in, float* __restrict__ ssum) {
    __shared__ float dps[H2];
    __shared__ float was[H2];
    __shared__ float ss[CH];
    int n = blockIdx.y;
    int t0 = blockIdx.x * CH;
    int len = lengths[n];
    if (t0 >= len) return;
    int kmax = min(CH, len - t0);
    int tid = threadIdx.x;

    for (int i = tid; i < H2; i += 256) {
        dps[i] = dp[(size_t)n * H2 + i];
        was[i] = Wattn[i];
    }
    if (tid < CH) ss[tid] = 0.0f;
    __syncthreads();

    int warp = tid >> 5, lane = tid & 31;
    float bb = battn[0];
#pragma unroll
    for (int rep = 0; rep < CH / 8; rep++) {
        int lt = warp + rep * 8;
        if (lt < kmax) {
            const float4* row = (const float4*)(attW + ((size_t)n * TT + t0 + lt) * H2);
            const float4* d4p = (const float4*)dps;
            const float4* w4p = (const float4*)was;
            float s = 0.0f;
#pragma unroll
            for (int it = 0; it < 8; it++) {
                int i = it * 32 + lane;
                float4 v = row[i];
                float4 dd = d4p[i];
                float4 ww = w4p[i];
                s += approx_tanh(v.x + dd.x) * ww.x
                   + approx_tanh(v.y + dd.y) * ww.y
                   + approx_tanh(v.z + dd.z) * ww.z
                   + approx_tanh(v.w + dd.w) * ww.w;
            }
#pragma unroll
            for (int o = 16; o; o >>= 1) s += __shfl_xor_sync(0xffffffffu, s, o);
            if (lane == 0) ss[lt] = __expf(s + bb);
        }
    }
    __syncthreads();

    if (warp == 0) {
        float v = (lane < CH) ? ss[lane] : 0.0f;
#pragma unroll
        for (int o = 16; o; o >>= 1) v += __shfl_xor_sync(0xffffffffu, v, o);
        if (lane == 0) atomicAdd(&ssum[n], v);
    }

    int h = tid * 4;
    const float* ebase = enc + (size_t)n * TT * H2 + (size_t)t0 * H2 + h;
    float ax = 0.f, ay = 0.f, az = 0.f, aw = 0.f;
#pragma unroll 4
    for (int t = 0; t < kmax; t++) {
        float w = ss[t];
        float4 e = *(const float4*)(ebase + (size_t)t * H2);
        ax += w * e.x; ay += w * e.y; az += w * e.z; aw += w * e.w;
    }
    red4(&dec_in[(size_t)n * H4 + h], ax, ay, az, aw);
}

// ---------------------------------------------------------------------------
// Host launch
// ---------------------------------------------------------------------------
static inline GD make_gd(const float* A, int lda, int mode, const float* W,
                         float* C, int M, int K, int KS, int inner,
                         const float* ssum, const int* skip) {
    GD d;
    d.A = A; d.W = W; d.C = C; d.ssum = ssum; d.skip = skip;
    d.lda = lda; d.M = M; d.K = K; d.KS = KS; d.inner = inner; d.mode = mode;
    d.nCol = (M + 63) / 64;
    d.start = 0;
    d.nBlocks = d.nCol * (K / KS);
    return d;
}

static inline void launch_batch(GD* ds, int n) {
    GemmBatch P;
    int start = 0;
    for (int i = 0; i < n; i++) {
        ds[i].start = start;
        start += ds[i].nBlocks;
        P.d[i] = ds[i];
    }
    for (int i = n; i < 4; i++) P.d[i] = P.d[n - 1];
    P.n = n;
    multi_gemm_kernel<<<start, 128>>>(P);
}

extern "C" void kernel_launch(void* const* d_in, const int* in_sizes, int n_in,
                              void* d_out, int out_size) {
    const float* input_enc   = (const float*)d_in[0];
    const float* attW_enc    = (const float*)d_in[1];
    const float* input_dec   = (const float*)d_in[2];
    const int*   lengths     = (const int*)  d_in[3];
    const float* hidden_att  = (const float*)d_in[4];
    const float* hidden_dec1 = (const float*)d_in[5];
    const float* hidden_dec2 = (const float*)d_in[6];
    const float* W_pre1 = (const float*)d_in[7];
    const float* b_pre1 = (const float*)d_in[8];
    const float* W_pre2 = (const float*)d_in[9];
    const float* b_pre2 = (const float*)d_in[10];
    const float* Wih_att = (const float*)d_in[11];
    const float* Whh_att = (const float*)d_in[12];
    const float* bih_att = (const float*)d_in[13];
    const float* bhh_att = (const float*)d_in[14];
    const float* W_ld  = (const float*)d_in[15];
    const float* b_ld  = (const float*)d_in[16];
    const float* W_attn = (const float*)d_in[17];
    const float* b_attn = (const float*)d_in[18];
    const float* W_sc  = (const float*)d_in[19];
    const float* b_sc  = (const float*)d_in[20];
    const float* Wih_d1 = (const float*)d_in[21];
    const float* Whh_d1 = (const float*)d_in[22];
    const float* bih_d1 = (const float*)d_in[23];
    const float* bhh_d1 = (const float*)d_in[24];
    const float* Wih_d2 = (const float*)d_in[25];
    const float* Whh_d2 = (const float*)d_in[26];
    const float* bih_d2 = (const float*)d_in[27];
    const float* bhh_d2 = (const float*)d_in[28];
    const float* W_out = (const float*)d_in[29];
    const float* b_out = (const float*)d_in[30];

    float* out = (float*)d_out;

    float* sc = nullptr;
    cudaGetSymbolAddress((void**)&sc, g_scratch);

    float* gi_att = sc + OFF_GI_ATT;
    float* gh_att = sc + OFF_GH_ATT;
    float* gi_d1  = sc + OFF_GI_D1;
    float* gh_d1  = sc + OFF_GH_D1;
    float* gi_d2  = sc + OFF_GI_D2;
    float* gh_d2  = sc + OFF_GH_D2;
    float* pre_a  = sc + OFF_PRE_A;
    float* pre    = sc + OFF_PRE;
    float* dp     = sc + OFF_DP;
    float* resid_sc = sc + OFF_RESID_SC;
    float* resid  = sc + OFF_RESID;
    float* resid2 = sc + OFF_RESID2;
    float* dec_in = sc + OFF_DECIN;
    float* ssum   = sc + OFF_SSUM;
    const int* flags = (const int*)(sc + OFF_FLAGS);

    bool full_out = (out_size >= NB * RR * OO + 3 * NB * H2);
    float* h_att_out = full_out ? out + NB * RR * OO : sc + OFF_HATT;
    float* h_d1_out  = full_out ? h_att_out + NB * H2 : sc + OFF_HD1;
    float* h_d2_out  = full_out ? h_d1_out + NB * H2 : sc + OFF_HD2;

    // 0) flags + zero/broadcast init
    precheck_kernel<<<3, 1024>>>(hidden_att, hidden_dec1, hidden_dec2);
    init_kernel<<<(INIT_TOTAL + 255) / 256, 256>>>(out, b_pre1, b_pre2, b_ld, b_sc, b_out);

    // 1) stage A: input-only dependencies (16 + 3*192 CTAs; gh skipped when hidden==0)
    {
        GD ds[4] = {
            make_gd(input_dec,   OO, 0, W_pre1,  pre_a,  H2, OO,   80, 16, nullptr, nullptr),
            make_gd(hidden_att,  H2, 0, Whh_att, gh_att, H3, H2,  256, 32, nullptr, flags + 0),
            make_gd(hidden_dec1, H2, 0, Whh_d1,  gh_d1,  H3, H2,  256, 32, nullptr, flags + 1),
            make_gd(hidden_dec2, H2, 0, Whh_d2,  gh_d2,  H3, H2,  256, 32, nullptr, flags + 2),
        };
        launch_batch(ds, 4);
    }
    // 2) pre = relu(pre_a) @ W_pre2^T + b2   (128 CTAs)
    {
        GD ds[1] = { make_gd(pre_a, H2, 1, W_pre2, pre, HH, H2, 64, 32, nullptr, nullptr) };
        launch_batch(ds, 1);
    }
    // 3) gi_att = relu(pre) @ Wih_att^T   (384 CTAs)
    {
        GD ds[1] = { make_gd(pre, HH, 1, Wih_att, gi_att, H3, HH, 64, 32, nullptr, nullptr) };
        launch_batch(ds, 1);
    }
    // 4) h_att
    gru_combine_kernel<<<(NB * H2 + 255) / 256, 256>>>(
        gi_att, gh_att, bih_att, bhh_att, hidden_att, h_att_out, nullptr, dec_in, 1);
    // 5) dec_proj   (256 CTAs)
    {
        GD ds[1] = { make_gd(h_att_out, H2, 0, W_ld, dp, H2, H2, 64, 32, nullptr, nullptr) };
        launch_batch(ds, 1);
    }
    // 6) fused attention (25 x 64 blocks)
    attn_fused_kernel<<<dim3(TT / CH, NB), 256>>>(attW_enc, input_enc, dp,
                                                  W_attn, b_attn, lengths,
                                                  dec_in, ssum);
    // 7) short-cut + decoder GRU 1 input gates (mode 2 normalizes attn half; 1024 CTAs)
    {
        GD ds[2] = {
            make_gd(dec_in, H4, 2, W_sc,   resid_sc, H2, H4, 128, 32, ssum, nullptr),
            make_gd(dec_in, H4, 2, Wih_d1, gi_d1,    H3, H4, 128, 32, ssum, nullptr),
        };
        launch_batch(ds, 2);
    }
    gru_combine_kernel<<<(NB * H2 + 255) / 256, 256>>>(
        gi_d1, gh_d1, bih_d1, bhh_d1, hidden_dec1, h_d1_out, resid_sc, resid, 2);
    // 8) decoder GRU 2   (768 CTAs)
    {
        GD ds[1] = { make_gd(resid, H2, 0, Wih_d2, gi_d2, H3, H2, 64, 32, nullptr, nullptr) };
        launch_batch(ds, 1);
    }
    gru_combine_kernel<<<(NB * H2 + 255) / 256, 256>>>(
        gi_d2, gh_d2, bih_d2, bhh_d2, hidden_dec2, h_d2_out, resid, resid2, 2);
    // 9) output projection   (96 CTAs)
    {
        GD ds[1] = { make_gd(resid2, H2, 0, W_out, out, RR * OO, H2, 32, 32, nullptr, nullptr) };
        launch_batch(ds, 1);
    }
}

// round 7
// speedup vs baseline: 3.0252x; 1.0537x over previous
#include <cuda_runtime.h>
#include <math.h>

// ---------------------------------------------------------------------------
// Problem constants
// ---------------------------------------------------------------------------
#define NB   64
#define TT   800
#define HH   512
#define H2   1024
#define H3   3072   // 3*H2
#define H4   2048   // 4*H
#define OO   80
#define RR   2

typedef unsigned long long ull;

// ---------------------------------------------------------------------------
// Scratch
// ---------------------------------------------------------------------------
#define GSZ       (NB * H3)
#define OFF_GI_ATT   0
#define OFF_GH_ATT   (1 * GSZ)
#define OFF_GI_D1    (2 * GSZ)
#define OFF_GH_D1    (3 * GSZ)
#define OFF_GI_D2    (4 * GSZ)
#define OFF_GH_D2    (5 * GSZ)
#define OFF_PRE_A    (6 * GSZ)
#define OFF_PRE      (OFF_PRE_A   + NB * H2)
#define OFF_DP       (OFF_PRE     + NB * HH)
#define OFF_RESID_SC (OFF_DP      + NB * H2)
#define OFF_RESID    (OFF_RESID_SC+ NB * H2)
#define OFF_RESID2   (OFF_RESID   + NB * H2)
#define OFF_DECIN    (OFF_RESID2  + NB * H2)
#define OFF_SSUM     (OFF_DECIN   + NB * H4)
#define OFF_FLAGS    (OFF_SSUM    + 64)
#define OFF_HATT     (OFF_FLAGS   + 16)
#define OFF_HD1      (OFF_HATT    + NB * H2)
#define OFF_HD2      (OFF_HD1     + NB * H2)
#define SCRATCH_TOTAL (OFF_HD2    + NB * H2)

__device__ float g_scratch[SCRATCH_TOTAL];

// ---------------------------------------------------------------------------
// Math helpers
// ---------------------------------------------------------------------------
__device__ __forceinline__ float fast_tanh(float x) {
    float e = __expf(2.0f * x);
    return 1.0f - 2.0f / (e + 1.0f);
}
__device__ __forceinline__ float approx_tanh(float x) {
    float y;
    asm("tanh.approx.f32 %0, %1;" : "=f"(y) : "f"(x));
    return y;
}
__device__ __forceinline__ float fast_sigmoid(float x) {
    return 1.0f / (1.0f + __expf(-x));
}

__device__ __forceinline__ ull pk2(float x, float y) {
    ull r;
    asm("mov.b64 %0, {%1, %2};" : "=l"(r) : "f"(x), "f"(y));
    return r;
}
__device__ __forceinline__ void upk2(ull v, float& x, float& y) {
    asm("mov.b64 {%0, %1}, %2;" : "=f"(x), "=f"(y) : "l"(v));
}
__device__ __forceinline__ void ffma2(ull& d, ull a, ull b) {
    asm("fma.rn.f32x2 %0, %1, %2, %0;" : "+l"(d) : "l"(a), "l"(b));
}
__device__ __forceinline__ void red4(float* p, float x, float y, float z, float w) {
    asm volatile("red.global.add.v4.f32 [%0], {%1,%2,%3,%4};"
                 :: "l"(p), "f"(x), "f"(y), "f"(z), "f"(w) : "memory");
}

// ---------------------------------------------------------------------------
// Precheck: flags[b] = any nonzero in hidden matrix b
// ---------------------------------------------------------------------------
__global__ void precheck_kernel(const float* __restrict__ h0,
                                const float* __restrict__ h1,
                                const float* __restrict__ h2) {
    const float* p = (blockIdx.x == 0) ? h0 : ((blockIdx.x == 1) ? h1 : h2);
    int any = 0;
    for (int i = threadIdx.x; i < NB * H2; i += 1024)
        any |= (p[i] != 0.0f);
    int r = __syncthreads_or(any);
    if (threadIdx.x == 0)
        ((int*)(g_scratch + OFF_FLAGS))[blockIdx.x] = r;
}

// ---------------------------------------------------------------------------
// Init: zero gate buffers + dec_in attn half + ssum, broadcast biases
// ---------------------------------------------------------------------------
#define INIT_TOTAL (6 * GSZ + NB * H2 + NB * HH + NB * H2 + NB * H2 + NB * RR * OO + NB * H2 + 64)

__global__ void init_kernel(float* __restrict__ out,
                            const float* __restrict__ b_pre1,
                            const float* __restrict__ b_pre2,
                            const float* __restrict__ b_ld,
                            const float* __restrict__ b_sc,
                            const float* __restrict__ b_out) {
    int idx = blockIdx.x * 256 + threadIdx.x;
    if (idx < 6 * GSZ) { g_scratch[idx] = 0.0f; return; }
    idx -= 6 * GSZ;
    if (idx < NB * H2) { g_scratch[OFF_PRE_A + idx] = b_pre1[idx & (H2 - 1)]; return; }
    idx -= NB * H2;
    if (idx < NB * HH) { g_scratch[OFF_PRE + idx] = b_pre2[idx & (HH - 1)]; return; }
    idx -= NB * HH;
    if (idx < NB * H2) { g_scratch[OFF_DP + idx] = b_ld[idx & (H2 - 1)]; return; }
    idx -= NB * H2;
    if (idx < NB * H2) { g_scratch[OFF_RESID_SC + idx] = b_sc[idx & (H2 - 1)]; return; }
    idx -= NB * H2;
    if (idx < NB * RR * OO) { out[idx] = b_out[idx % (RR * OO)]; return; }
    idx -= NB * RR * OO;
    if (idx < NB * H2) {
        int n = idx >> 10, j = idx & (H2 - 1);
        g_scratch[OFF_DECIN + (size_t)n * H4 + j] = 0.0f;
        return;
    }
    idx -= NB * H2;
    if (idx < 64) { g_scratch[OFF_SSUM + idx] = 0.0f; return; }
}

// ---------------------------------------------------------------------------
// Batched skinny GEMM: C[64, M] += A'[64, K] * W[M, K]^T
// 64x64 tile, 128 threads, 8x4 per-thread, f32x2 row-pair accumulators.
// Two-level K with REGISTER PREFETCH double-buffering across smem refills.
// mode: 0 = identity, 1 = relu(A), 2 = divide cols k<1024 by ssum[row]
// Requires K % KS == 0, KS % inner == 0, inner in {16,32}.
// ---------------------------------------------------------------------------
#define GIN_MAX 32

struct GD {
    const float* A;
    const float* W;
    float* C;
    const float* ssum;
    const int* skip;
    int lda, M, K, KS, inner, mode, nCol, start, nBlocks;
};
struct GemmBatch { GD d[4]; int n; };

__global__ void __launch_bounds__(128, 4) multi_gemm_kernel(GemmBatch P) {
    __shared__ float As[GIN_MAX * 64];
    __shared__ float Ws[GIN_MAX * 64];

    int b = blockIdx.x;
    GD d = P.d[0];
#pragma unroll
    for (int i = 1; i < 4; i++) {
        if (i < P.n && b >= P.d[i].start) d = P.d[i];
    }
    if (d.skip && *d.skip == 0) return;

    int lb = b - d.start;
    int colBlock = lb % d.nCol;
    int kBlock = lb / d.nCol;
    int colBase = colBlock * 64;
    int k0 = kBlock * d.KS;

    int tid = threadIdx.x;
    int ty = tid >> 4;
    int tx = tid & 15;

    int arow = tid & 63;
    int half = tid >> 6;
    int wcol = tid & 63;
    int gc = colBase + wcol;
    bool wvalid = (gc < d.M);

    float wv = 1.0f;
    if (d.mode == 2) wv = 1.0f / fmaxf(d.ssum[arow], 1e-12f);

    const float* aptr = d.A + (size_t)arow * d.lda;
    const float* wptr = d.W + (size_t)(wvalid ? gc : 0) * d.K;

    ull acc[4][4];
#pragma unroll
    for (int p = 0; p < 4; p++)
#pragma unroll
        for (int j = 0; j < 4; j++) acc[p][j] = pk2(0.0f, 0.0f);

    int nref = d.KS / d.inner;
    int hk = d.inner >> 1;        // k-columns per thread-half
    int nf4 = hk >> 2;            // float4 loads per thread (2 or 4)
    const float4 z4 = make_float4(0.f, 0.f, 0.f, 0.f);

    float4 aq[4], wq[4];
    // prologue: load refill 0 into regs
#pragma unroll
    for (int q = 0; q < 4; q++) {
        if (q < nf4) {
            int kl = half * hk + q * 4;
            aq[q] = *(const float4*)(aptr + k0 + kl);
            wq[q] = wvalid ? *(const float4*)(wptr + k0 + kl) : z4;
        }
    }

    int kb = k0;
    for (int rf = 0; rf < nref; rf++) {
        // ---- store phase (transform applied here with current kb) ----
#pragma unroll
        for (int q = 0; q < 4; q++) {
            if (q < nf4) {
                int kl = half * hk + q * 4;
                float4 v = aq[q];
                if (d.mode == 1) {
                    v.x = fmaxf(v.x, 0.f); v.y = fmaxf(v.y, 0.f);
                    v.z = fmaxf(v.z, 0.f); v.w = fmaxf(v.w, 0.f);
                } else if (d.mode == 2 && (kb + kl) < H2) {
                    v.x *= wv; v.y *= wv; v.z *= wv; v.w *= wv;
                }
                As[(kl + 0) * 64 + arow] = v.x; As[(kl + 1) * 64 + arow] = v.y;
                As[(kl + 2) * 64 + arow] = v.z; As[(kl + 3) * 64 + arow] = v.w;
                float4 u = wq[q];
                Ws[(kl + 0) * 64 + wcol] = u.x; Ws[(kl + 1) * 64 + wcol] = u.y;
                Ws[(kl + 2) * 64 + wcol] = u.z; Ws[(kl + 3) * 64 + wcol] = u.w;
            }
        }
        __syncthreads();

        // ---- prefetch next refill into regs (overlaps compute below) ----
        if (rf + 1 < nref) {
            int kn = kb + d.inner;
#pragma unroll
            for (int q = 0; q < 4; q++) {
                if (q < nf4) {
                    int kl = half * hk + q * 4;
                    aq[q] = *(const float4*)(aptr + kn + kl);
                    wq[q] = wvalid ? *(const float4*)(wptr + kn + kl) : z4;
                }
            }
        }

        // ---- compute ----
#pragma unroll 4
        for (int kk = 0; kk < d.inner; kk++) {
            const float* ab = &As[kk * 64 + ty * 8];
            ulonglong2 Ap0 = *(const ulonglong2*)(ab);
            ulonglong2 Ap1 = *(const ulonglong2*)(ab + 4);
            float4 bv = *(const float4*)&Ws[kk * 64 + tx * 4];
            ull b0 = pk2(bv.x, bv.x);
            ull b1 = pk2(bv.y, bv.y);
            ull b2 = pk2(bv.z, bv.z);
            ull b3 = pk2(bv.w, bv.w);
            ffma2(acc[0][0], Ap0.x, b0); ffma2(acc[0][1], Ap0.x, b1);
            ffma2(acc[0][2], Ap0.x, b2); ffma2(acc[0][3], Ap0.x, b3);
            ffma2(acc[1][0], Ap0.y, b0); ffma2(acc[1][1], Ap0.y, b1);
            ffma2(acc[1][2], Ap0.y, b2); ffma2(acc[1][3], Ap0.y, b3);
            ffma2(acc[2][0], Ap1.x, b0); ffma2(acc[2][1], Ap1.x, b1);
            ffma2(acc[2][2], Ap1.x, b2); ffma2(acc[2][3], Ap1.x, b3);
            ffma2(acc[3][0], Ap1.y, b0); ffma2(acc[3][1], Ap1.y, b1);
            ffma2(acc[3][2], Ap1.y, b2); ffma2(acc[3][3], Ap1.y, b3);
        }
        __syncthreads();
        kb += d.inner;
    }

    int col = colBase + tx * 4;
    if (col < d.M) {
#pragma unroll
        for (int p = 0; p < 4; p++) {
            int r0 = ty * 8 + 2 * p;
            float lo0, hi0, lo1, hi1, lo2, hi2, lo3, hi3;
            upk2(acc[p][0], lo0, hi0);
            upk2(acc[p][1], lo1, hi1);
            upk2(acc[p][2], lo2, hi2);
            upk2(acc[p][3], lo3, hi3);
            red4(&d.C[(size_t)r0 * d.M + col], lo0, lo1, lo2, lo3);
            red4(&d.C[(size_t)(r0 + 1) * d.M + col], hi0, hi1, hi2, hi3);
        }
    }
}

// ---------------------------------------------------------------------------
// GRU combine
// ---------------------------------------------------------------------------
__global__ void gru_combine_kernel(const float* __restrict__ gi,
                                   const float* __restrict__ gh,
                                   const float* __restrict__ bih,
                                   const float* __restrict__ bhh,
                                   const float* __restrict__ hprev,
                                   float* __restrict__ hout,
                                   const float* __restrict__ extra_in,
                                   float* __restrict__ extra_out,
                                   int mode) {
    int idx = blockIdx.x * 256 + threadIdx.x;
    if (idx >= NB * H2) return;
    int n = idx >> 10;
    int j = idx & (H2 - 1);
    const float* gin = gi + (size_t)n * H3;
    const float* ghn = gh + (size_t)n * H3;
    float ir = gin[j]          + bih[j];
    float iz = gin[j + H2]     + bih[j + H2];
    float in_ = gin[j + 2*H2]  + bih[j + 2*H2];
    float hr = ghn[j]          + bhh[j];
    float hz = ghn[j + H2]     + bhh[j + H2];
    float hn = ghn[j + 2*H2]   + bhh[j + 2*H2];
    float r = fast_sigmoid(ir + hr);
    float z = fast_sigmoid(iz + hz);
    float nn = fast_tanh(in_ + r * hn);
    float h = (1.0f - z) * nn + z * hprev[idx];
    hout[idx] = h;
    if (mode == 1) {
        extra_out[(size_t)n * H4 + H2 + j] = h;
    } else if (mode == 2) {
        extra_out[idx] = extra_in[idx] + h;
    }
}

// ---------------------------------------------------------------------------
// Fused attention: per (n, 32-t chunk) block: scores + unnormalized apply
// ---------------------------------------------------------------------------
#define CH 32

__global__ void __launch_bounds__(256) attn_fused_kernel(
    const float* __restrict__ attW, const float* __restrict__ enc,
    const float* __restrict__ dp, const float* __restrict__ Wattn,
    const float* __restrict__ battn, const int* __restrict__ lengths,
    float* __restrict__ dec_in, float* __restrict__ ssum) {
    __shared__ float dps[H2];
    __shared__ float was[H2];
    __shared__ float ss[CH];
    int n = blockIdx.y;
    int t0 = blockIdx.x * CH;
    int len = lengths[n];
    if (t0 >= len) return;
    int kmax = min(CH, len - t0);
    int tid = threadIdx.x;

    for (int i = tid; i < H2; i += 256) {
        dps[i] = dp[(size_t)n * H2 + i];
        was[i] = Wattn[i];
    }
    if (tid < CH) ss[tid] = 0.0f;
    __syncthreads();

    int warp = tid >> 5, lane = tid & 31;
    float bb = battn[0];
#pragma unroll
    for (int rep = 0; rep < CH / 8; rep++) {
        int lt = warp + rep * 8;
        if (lt < kmax) {
            const float4* row = (const float4*)(attW + ((size_t)n * TT + t0 + lt) * H2);
            const float4* d4p = (const float4*)dps;
            const float4* w4p = (const float4*)was;
            float s = 0.0f;
#pragma unroll
            for (int it = 0; it < 8; it++) {
                int i = it * 32 + lane;
                float4 v = row[i];
                float4 dd = d4p[i];
                float4 ww = w4p[i];
                s += approx_tanh(v.x + dd.x) * ww.x
                   + approx_tanh(v.y + dd.y) * ww.y
                   + approx_tanh(v.z + dd.z) * ww.z
                   + approx_tanh(v.w + dd.w) * ww.w;
            }
#pragma unroll
            for (int o = 16; o; o >>= 1) s += __shfl_xor_sync(0xffffffffu, s, o);
            if (lane == 0) ss[lt] = __expf(s + bb);
        }
    }
    __syncthreads();

    if (warp == 0) {
        float v = (lane < CH) ? ss[lane] : 0.0f;
#pragma unroll
        for (int o = 16; o; o >>= 1) v += __shfl_xor_sync(0xffffffffu, v, o);
        if (lane == 0) atomicAdd(&ssum[n], v);
    }

    int h = tid * 4;
    const float* ebase = enc + (size_t)n * TT * H2 + (size_t)t0 * H2 + h;
    float ax = 0.f, ay = 0.f, az = 0.f, aw = 0.f;
#pragma unroll 4
    for (int t = 0; t < kmax; t++) {
        float w = ss[t];
        float4 e = *(const float4*)(ebase + (size_t)t * H2);
        ax += w * e.x; ay += w * e.y; az += w * e.z; aw += w * e.w;
    }
    red4(&dec_in[(size_t)n * H4 + h], ax, ay, az, aw);
}

// ---------------------------------------------------------------------------
// Host launch
// ---------------------------------------------------------------------------
static inline GD make_gd(const float* A, int lda, int mode, const float* W,
                         float* C, int M, int K, int KS, int inner,
                         const float* ssum, const int* skip) {
    GD d;
    d.A = A; d.W = W; d.C = C; d.ssum = ssum; d.skip = skip;
    d.lda = lda; d.M = M; d.K = K; d.KS = KS; d.inner = inner; d.mode = mode;
    d.nCol = (M + 63) / 64;
    d.start = 0;
    d.nBlocks = d.nCol * (K / KS);
    return d;
}

static inline void launch_batch(GD* ds, int n) {
    GemmBatch P;
    int start = 0;
    for (int i = 0; i < n; i++) {
        ds[i].start = start;
        start += ds[i].nBlocks;
        P.d[i] = ds[i];
    }
    for (int i = n; i < 4; i++) P.d[i] = P.d[n - 1];
    P.n = n;
    multi_gemm_kernel<<<start, 128>>>(P);
}

extern "C" void kernel_launch(void* const* d_in, const int* in_sizes, int n_in,
                              void* d_out, int out_size) {
    const float* input_enc   = (const float*)d_in[0];
    const float* attW_enc    = (const float*)d_in[1];
    const float* input_dec   = (const float*)d_in[2];
    const int*   lengths     = (const int*)  d_in[3];
    const float* hidden_att  = (const float*)d_in[4];
    const float* hidden_dec1 = (const float*)d_in[5];
    const float* hidden_dec2 = (const float*)d_in[6];
    const float* W_pre1 = (const float*)d_in[7];
    const float* b_pre1 = (const float*)d_in[8];
    const float* W_pre2 = (const float*)d_in[9];
    const float* b_pre2 = (const float*)d_in[10];
    const float* Wih_att = (const float*)d_in[11];
    const float* Whh_att = (const float*)d_in[12];
    const float* bih_att = (const float*)d_in[13];
    const float* bhh_att = (const float*)d_in[14];
    const float* W_ld  = (const float*)d_in[15];
    const float* b_ld  = (const float*)d_in[16];
    const float* W_attn = (const float*)d_in[17];
    const float* b_attn = (const float*)d_in[18];
    const float* W_sc  = (const float*)d_in[19];
    const float* b_sc  = (const float*)d_in[20];
    const float* Wih_d1 = (const float*)d_in[21];
    const float* Whh_d1 = (const float*)d_in[22];
    const float* bih_d1 = (const float*)d_in[23];
    const float* bhh_d1 = (const float*)d_in[24];
    const float* Wih_d2 = (const float*)d_in[25];
    const float* Whh_d2 = (const float*)d_in[26];
    const float* bih_d2 = (const float*)d_in[27];
    const float* bhh_d2 = (const float*)d_in[28];
    const float* W_out = (const float*)d_in[29];
    const float* b_out = (const float*)d_in[30];

    float* out = (float*)d_out;

    float* sc = nullptr;
    cudaGetSymbolAddress((void**)&sc, g_scratch);

    float* gi_att = sc + OFF_GI_ATT;
    float* gh_att = sc + OFF_GH_ATT;
    float* gi_d1  = sc + OFF_GI_D1;
    float* gh_d1  = sc + OFF_GH_D1;
    float* gi_d2  = sc + OFF_GI_D2;
    float* gh_d2  = sc + OFF_GH_D2;
    float* pre_a  = sc + OFF_PRE_A;
    float* pre    = sc + OFF_PRE;
    float* dp     = sc + OFF_DP;
    float* resid_sc = sc + OFF_RESID_SC;
    float* resid  = sc + OFF_RESID;
    float* resid2 = sc + OFF_RESID2;
    float* dec_in = sc + OFF_DECIN;
    float* ssum   = sc + OFF_SSUM;
    const int* flags = (const int*)(sc + OFF_FLAGS);

    bool full_out = (out_size >= NB * RR * OO + 3 * NB * H2);
    float* h_att_out = full_out ? out + NB * RR * OO : sc + OFF_HATT;
    float* h_d1_out  = full_out ? h_att_out + NB * H2 : sc + OFF_HD1;
    float* h_d2_out  = full_out ? h_d1_out + NB * H2 : sc + OFF_HD2;

    // 0) flags + zero/broadcast init
    precheck_kernel<<<3, 1024>>>(hidden_att, hidden_dec1, hidden_dec2);
    init_kernel<<<(INIT_TOTAL + 255) / 256, 256>>>(out, b_pre1, b_pre2, b_ld, b_sc, b_out);

    // 1) stage A: input-only dependencies (80 real CTAs + skipped Whh blocks)
    {
        GD ds[4] = {
            make_gd(input_dec,   OO, 0, W_pre1,  pre_a,  H2, OO,   16, 16, nullptr, nullptr),
            make_gd(hidden_att,  H2, 0, Whh_att, gh_att, H3, H2,  256, 32, nullptr, flags + 0),
            make_gd(hidden_dec1, H2, 0, Whh_d1,  gh_d1,  H3, H2,  256, 32, nullptr, flags + 1),
            make_gd(hidden_dec2, H2, 0, Whh_d2,  gh_d2,  H3, H2,  256, 32, nullptr, flags + 2),
        };
        launch_batch(ds, 4);
    }
    // 2) pre = relu(pre_a) @ W_pre2^T + b2   (256 CTAs)
    {
        GD ds[1] = { make_gd(pre_a, H2, 1, W_pre2, pre, HH, H2, 32, 32, nullptr, nullptr) };
        launch_batch(ds, 1);
    }
    // 3) gi_att = relu(pre) @ Wih_att^T   (384 CTAs, nref=2 prefetch)
    {
        GD ds[1] = { make_gd(pre, HH, 1, Wih_att, gi_att, H3, HH, 64, 32, nullptr, nullptr) };
        launch_batch(ds, 1);
    }
    // 4) h_att
    gru_combine_kernel<<<(NB * H2 + 255) / 256, 256>>>(
        gi_att, gh_att, bih_att, bhh_att, hidden_att, h_att_out, nullptr, dec_in, 1);
    // 5) dec_proj   (256 CTAs, nref=2)
    {
        GD ds[1] = { make_gd(h_att_out, H2, 0, W_ld, dp, H2, H2, 64, 32, nullptr, nullptr) };
        launch_batch(ds, 1);
    }
    // 6) fused attention (25 x 64 blocks)
    attn_fused_kernel<<<dim3(TT / CH, NB), 256>>>(attW_enc, input_enc, dp,
                                                  W_attn, b_attn, lengths,
                                                  dec_in, ssum);
    // 7) short-cut + decoder GRU 1 input gates (1024 CTAs, nref=4)
    {
        GD ds[2] = {
            make_gd(dec_in, H4, 2, W_sc,   resid_sc, H2, H4, 128, 32, ssum, nullptr),
            make_gd(dec_in, H4, 2, Wih_d1, gi_d1,    H3, H4, 128, 32, ssum, nullptr),
        };
        launch_batch(ds, 2);
    }
    gru_combine_kernel<<<(NB * H2 + 255) / 256, 256>>>(
        gi_d1, gh_d1, bih_d1, bhh_d1, hidden_dec1, h_d1_out, resid_sc, resid, 2);
    // 8) decoder GRU 2   (384 CTAs, nref=4)
    {
        GD ds[1] = { make_gd(resid, H2, 0, Wih_d2, gi_d2, H3, H2, 128, 32, nullptr, nullptr) };
        launch_batch(ds, 1);
    }
    gru_combine_kernel<<<(NB * H2 + 255) / 256, 256>>>(
        gi_d2, gh_d2, bih_d2, bhh_d2, hidden_dec2, h_d2_out, resid, resid2, 2);
    // 9) output projection   (192 CTAs)
    {
        GD ds[1] = { make_gd(resid2, H2, 0, W_out, out, RR * OO, H2, 16, 16, nullptr, nullptr) };
        launch_batch(ds, 1);
    }
}